// round 3
// baseline (speedup 1.0000x reference)
#include <cuda_runtime.h>
#include <cuda_bf16.h>

// Problem constants
#define NN   50000
#define EE   1600000
#define RR   16
#define NB   4
#define HH   128
#define GG   64
#define NC   2

// ---------------- device scratch (static, no allocs) ----------------
__device__ unsigned int d_csr[EE];          // packed src | (type<<20)
__device__ int   d_rowptr[NN + 1];
__device__ int   d_deg[NN];
__device__ int   d_cursor[NN];
__device__ int   d_cnt[NN * RR];
__device__ float d_invcnt[NN * RR];
__device__ float d_z[(size_t)NN * 512];     // aggregated basis-space features
__device__ float d_h1[(size_t)NN * HH];
__device__ float d_h2[(size_t)NN * HH];
__device__ float d_pool[GG * HH];
__device__ float d_poolcnt[GG];

// ---------------- init ----------------
__global__ void zero_init_kernel() {
    int i = blockIdx.x * blockDim.x + threadIdx.x;
    if (i < NN * RR) d_cnt[i] = 0;
    if (i < NN) { d_deg[i] = 0; d_cursor[i] = 0; }
    if (i < GG * HH) d_pool[i] = 0.0f;
    if (i < GG) d_poolcnt[i] = 0.0f;
}

// ---------------- CSR build ----------------
__global__ void count_kernel(const int* __restrict__ ei, const int* __restrict__ et) {
    int e = blockIdx.x * blockDim.x + threadIdx.x;
    if (e >= EE) return;
    int dst = __ldg(ei + EE + e);
    int t   = __ldg(et + e);
    atomicAdd(&d_deg[dst], 1);
    atomicAdd(&d_cnt[dst * RR + t], 1);
}

__global__ void scan_kernel() {   // 1 block, 1024 threads
    const int T = 1024;
    __shared__ int sh[T];
    int tid = threadIdx.x;
    int chunk = (NN + T - 1) / T;
    int start = tid * chunk;
    int endi  = start + chunk; if (endi > NN) endi = NN;
    int s = 0;
    for (int i = start; i < endi && start < NN; i++) s += d_deg[i];
    sh[tid] = (start < NN) ? s : 0;
    __syncthreads();
    for (int off = 1; off < T; off <<= 1) {
        int v = (tid >= off) ? sh[tid - off] : 0;
        __syncthreads();
        if (tid >= off) sh[tid] += v;
        __syncthreads();
    }
    int run = (tid == 0) ? 0 : sh[tid - 1];
    if (start < NN) {
        for (int i = start; i < endi; i++) { d_rowptr[i] = run; run += d_deg[i]; }
    }
    if (tid == T - 1) d_rowptr[NN] = sh[T - 1];
}

__global__ void invcnt_kernel() {
    int i = blockIdx.x * blockDim.x + threadIdx.x;
    if (i >= NN * RR) return;
    int c = d_cnt[i];
    d_invcnt[i] = 1.0f / (float)(c > 1 ? c : 1);
}

__global__ void scatter_kernel(const int* __restrict__ ei, const int* __restrict__ et) {
    int e = blockIdx.x * blockDim.x + threadIdx.x;
    if (e >= EE) return;
    int src = __ldg(ei + e);
    int dst = __ldg(ei + EE + e);
    int t   = __ldg(et + e);
    int pos = d_rowptr[dst] + atomicAdd(&d_cursor[dst], 1);
    d_csr[pos] = (unsigned)src | ((unsigned)t << 20);
}

// ---------------- per-layer aggregation: z[n, b*128 + j] ----------------
// one warp per node; lane covers 4 consecutive feature dims
__global__ void agg_kernel(int sel, const float* __restrict__ x0,
                           const float* __restrict__ comp /*[R,NB]*/) {
    __shared__ float s_comp[RR * NB];
    int tid = threadIdx.x;
    if (tid < RR * NB) s_comp[tid] = comp[tid];
    __syncthreads();

    int warp = (blockIdx.x * blockDim.x + tid) >> 5;
    int lane = tid & 31;
    if (warp >= NN) return;

    const float* X = (sel == 0) ? x0 : (sel == 1 ? d_h1 : d_h2);

    int beg = d_rowptr[warp];
    int end = d_rowptr[warp + 1];
    float inv_t = (lane < RR) ? d_invcnt[warp * RR + lane] : 0.0f;

    float4 acc0 = {0,0,0,0}, acc1 = {0,0,0,0}, acc2 = {0,0,0,0}, acc3 = {0,0,0,0};

    #pragma unroll 4
    for (int i = beg; i < end; i++) {
        unsigned p = d_csr[i];
        int src = (int)(p & 0xFFFFFu);
        int t   = (int)(p >> 20);
        float ic = __shfl_sync(0xffffffffu, inv_t, t);
        float4 v = *(const float4*)(X + (size_t)src * HH + lane * 4);
        float w0 = s_comp[t * NB + 0] * ic;
        float w1 = s_comp[t * NB + 1] * ic;
        float w2 = s_comp[t * NB + 2] * ic;
        float w3 = s_comp[t * NB + 3] * ic;
        acc0.x += w0 * v.x; acc0.y += w0 * v.y; acc0.z += w0 * v.z; acc0.w += w0 * v.w;
        acc1.x += w1 * v.x; acc1.y += w1 * v.y; acc1.z += w1 * v.z; acc1.w += w1 * v.w;
        acc2.x += w2 * v.x; acc2.y += w2 * v.y; acc2.z += w2 * v.z; acc2.w += w2 * v.w;
        acc3.x += w3 * v.x; acc3.y += w3 * v.y; acc3.z += w3 * v.z; acc3.w += w3 * v.w;
    }

    float* zp = d_z + (size_t)warp * 512 + lane * 4;
    *(float4*)(zp + 0 * HH) = acc0;
    *(float4*)(zp + 1 * HH) = acc1;
    *(float4*)(zp + 2 * HH) = acc2;
    *(float4*)(zp + 3 * HH) = acc3;
}

// ---------------- per-layer GEMM: out = [z|x] @ [bases;root] + bias (+relu) ----
// C[N,128], K=640. 64x128 block tile, 256 threads, 8x4 per thread.
__global__ void gemm_kernel(int sel, const float* __restrict__ x0, int osel,
                            const float* __restrict__ bases /*[512,128]*/,
                            const float* __restrict__ root  /*[128,128]*/,
                            const float* __restrict__ bias, int relu) {
    __shared__ float Ash[64][16];
    __shared__ float Wsh[16][128];

    const float* X = (sel == 0) ? x0 : (sel == 1 ? d_h1 : d_h2);
    float* OUT = (osel == 1) ? d_h1 : d_h2;

    int tid = threadIdx.x;
    int tx = tid & 31;           // col group (4 cols)
    int ty = tid >> 5;           // row group (8 rows)
    int blk = blockIdx.x;
    int row0 = blk * 64;

    float4 acc[8];
    #pragma unroll
    for (int i = 0; i < 8; i++) acc[i] = make_float4(0.f, 0.f, 0.f, 0.f);

    // A-load indices: each thread loads one float4 of the 64x16 tile
    int am  = tid >> 2;          // 0..63
    int ak4 = (tid & 3) * 4;     // 0,4,8,12
    // W-load indices: each thread loads two float4 of the 16x128 tile
    int wr = tid >> 4;           // 0..15
    int wc = (tid & 15) * 8;     // 0..120 step 8

    for (int kt = 0; kt < 40; kt++) {
        // ---- load A tile
        {
            int gm = row0 + am;
            float4 v = make_float4(0.f, 0.f, 0.f, 0.f);
            if (gm < NN) {
                if (kt < 32) v = *(const float4*)(d_z + (size_t)gm * 512 + kt * 16 + ak4);
                else         v = *(const float4*)(X   + (size_t)gm * 128 + (kt - 32) * 16 + ak4);
            }
            *(float4*)&Ash[am][ak4] = v;
        }
        // ---- load W tile
        {
            int gk = kt * 16 + wr;
            const float* wsrc = (kt < 32) ? (bases + (size_t)gk * 128)
                                          : (root + (size_t)(gk - 512) * 128);
            float4 wa = __ldg((const float4*)(wsrc + wc));
            float4 wb = __ldg((const float4*)(wsrc + wc + 4));
            *(float4*)&Wsh[wr][wc]     = wa;
            *(float4*)&Wsh[wr][wc + 4] = wb;
        }
        __syncthreads();

        #pragma unroll
        for (int kk = 0; kk < 16; kk++) {
            float4 w = *(const float4*)&Wsh[kk][tx * 4];
            #pragma unroll
            for (int i = 0; i < 8; i++) {
                float a = Ash[ty * 8 + i][kk];
                acc[i].x += a * w.x; acc[i].y += a * w.y;
                acc[i].z += a * w.z; acc[i].w += a * w.w;
            }
        }
        __syncthreads();
    }

    float4 b4 = *(const float4*)(bias + tx * 4);
    #pragma unroll
    for (int i = 0; i < 8; i++) {
        int gm = row0 + ty * 8 + i;
        if (gm >= NN) continue;
        float4 v;
        v.x = acc[i].x + b4.x; v.y = acc[i].y + b4.y;
        v.z = acc[i].z + b4.z; v.w = acc[i].w + b4.w;
        if (relu) {
            v.x = fmaxf(v.x, 0.f); v.y = fmaxf(v.y, 0.f);
            v.z = fmaxf(v.z, 0.f); v.w = fmaxf(v.w, 0.f);
        }
        *(float4*)(OUT + (size_t)gm * 128 + tx * 4) = v;
    }
}

// ---------------- pooling ----------------
__global__ void pool_kernel(const int* __restrict__ batch) {
    int warp = (blockIdx.x * blockDim.x + threadIdx.x) >> 5;
    int lane = threadIdx.x & 31;
    if (warp >= NN) return;
    int g = __ldg(batch + warp);
    float4 v = *(const float4*)(d_h1 + (size_t)warp * 128 + lane * 4);
    atomicAdd(&d_pool[g * 128 + lane * 4 + 0], v.x);
    atomicAdd(&d_pool[g * 128 + lane * 4 + 1], v.y);
    atomicAdd(&d_pool[g * 128 + lane * 4 + 2], v.z);
    atomicAdd(&d_pool[g * 128 + lane * 4 + 3], v.w);
    if (lane == 0) atomicAdd(&d_poolcnt[g], 1.0f);
}

__global__ void final_kernel(const int* __restrict__ rl,
                             const float* __restrict__ rel_emb,
                             const float* __restrict__ lw,   // [256,2]
                             const float* __restrict__ lb,   // [2]
                             float* __restrict__ out) {
    int t = threadIdx.x;
    if (t >= GG * NC) return;
    int g = t >> 1, c = t & 1;
    float cnt = d_poolcnt[g];
    float invc = 1.0f / (cnt > 1.0f ? cnt : 1.0f);
    const float* re = rel_emb + (size_t)rl[g] * 128;
    float s = 0.f;
    for (int j = 0; j < 128; j++) s += d_pool[g * 128 + j] * invc * lw[j * 2 + c];
    for (int j = 0; j < 128; j++) s += re[j] * lw[(128 + j) * 2 + c];
    out[g * 2 + c] = s + lb[c];
}

// ---------------- launch ----------------
extern "C" void kernel_launch(void* const* d_in, const int* in_sizes, int n_in,
                              void* d_out, int out_size) {
    const float* x      = (const float*)d_in[0];
    const int*   ei     = (const int*)d_in[1];
    const int*   et     = (const int*)d_in[2];
    const int*   batch  = (const int*)d_in[3];
    const int*   rl     = (const int*)d_in[4];
    const float* relemb = (const float*)d_in[6];
    const float* bases[3] = {(const float*)d_in[7],  (const float*)d_in[11], (const float*)d_in[15]};
    const float* comp[3]  = {(const float*)d_in[8],  (const float*)d_in[12], (const float*)d_in[16]};
    const float* root[3]  = {(const float*)d_in[9],  (const float*)d_in[13], (const float*)d_in[17]};
    const float* bias[3]  = {(const float*)d_in[10], (const float*)d_in[14], (const float*)d_in[18]};
    const float* lin_w  = (const float*)d_in[19];
    const float* lin_b  = (const float*)d_in[20];
    float* out = (float*)d_out;

    const int TB = 256;
    zero_init_kernel<<<(NN * RR + TB - 1) / TB, TB>>>();
    count_kernel<<<(EE + TB - 1) / TB, TB>>>(ei, et);
    scan_kernel<<<1, 1024>>>();
    invcnt_kernel<<<(NN * RR + TB - 1) / TB, TB>>>();
    scatter_kernel<<<(EE + TB - 1) / TB, TB>>>(ei, et);

    int aggBlocks  = (NN * 32 + TB - 1) / TB;
    int gemmBlocks = (NN + 63) / 64;

    // layer 1: in = x (sel 0), out = h1 (osel 1), relu
    agg_kernel<<<aggBlocks, TB>>>(0, x, comp[0]);
    gemm_kernel<<<gemmBlocks, TB>>>(0, x, 1, bases[0], root[0], bias[0], 1);
    // layer 2: in = h1 (sel 1), out = h2 (osel 2), relu
    agg_kernel<<<aggBlocks, TB>>>(1, x, comp[1]);
    gemm_kernel<<<gemmBlocks, TB>>>(1, x, 2, bases[1], root[1], bias[1], 1);
    // layer 3: in = h2 (sel 2), out = h1 (osel 1), no relu
    agg_kernel<<<aggBlocks, TB>>>(2, x, comp[2]);
    gemm_kernel<<<gemmBlocks, TB>>>(2, x, 1, bases[2], root[2], bias[2], 0);

    pool_kernel<<<aggBlocks, TB>>>(batch);
    final_kernel<<<1, 128>>>(rl, relemb, lin_w, lin_b, out);
}

// round 5
// speedup vs baseline: 1.4628x; 1.4628x over previous
#include <cuda_runtime.h>
#include <cuda_bf16.h>
#include <cstdint>

// Problem constants
#define NN   50000
#define EE   1600000
#define RR   16
#define NB   4
#define HH   128
#define GG   64
#define NC   2

#define KTOT 640
#define MTILE 128
#define NTILE 128
#define KCHUNK 64
#define NCHUNKS 10
#define GEMM_GRID ((NN + MTILE - 1) / MTILE)   // 391
#define GEMM_SMEM 65536

// ---------------- device scratch (static, no allocs) ----------------
__device__ unsigned int d_csr[EE];
__device__ int   d_rowptr[NN + 1];
__device__ int   d_deg[NN];
__device__ int   d_cursor[NN];
__device__ int   d_cnt[NN * RR];
__device__ float d_invcnt[NN * RR];
__device__ float d_z[(size_t)NN * 512];
__device__ float d_h1[(size_t)NN * HH];
__device__ float d_h2[(size_t)NN * HH];
__device__ float d_pool[GG * HH];
__device__ float d_poolcnt[GG];
// transposed + hi/lo split weights: [layer][n(128)][k(640)]
__device__ __nv_bfloat16 d_wt_hi[3 * NTILE * KTOT];
__device__ __nv_bfloat16 d_wt_lo[3 * NTILE * KTOT];

// ---------------- helpers ----------------
__device__ __forceinline__ uint32_t smem_u32(const void* p) {
    uint32_t a;
    asm("{ .reg .u64 t; cvta.to.shared.u64 t, %1; cvt.u32.u64 %0, t; }" : "=r"(a) : "l"(p));
    return a;
}
#define SW128(o) ((o) ^ (((o) >> 3) & 0x70))

__device__ __forceinline__ void split2(float a, float b, uint32_t& hi, uint32_t& lo) {
    __nv_bfloat16 ha = __float2bfloat16(a), hb = __float2bfloat16(b);
    float fa = __bfloat162float(ha), fb = __bfloat162float(hb);
    __nv_bfloat16 la = __float2bfloat16(a - fa), lb = __float2bfloat16(b - fb);
    hi = (uint32_t)__bfloat16_as_ushort(ha) | ((uint32_t)__bfloat16_as_ushort(hb) << 16);
    lo = (uint32_t)__bfloat16_as_ushort(la) | ((uint32_t)__bfloat16_as_ushort(lb) << 16);
}

__device__ __forceinline__ void ldsm_x4(uint32_t* r, uint32_t addr) {
    asm volatile("ldmatrix.sync.aligned.m8n8.x4.shared.b16 {%0,%1,%2,%3}, [%4];"
                 : "=r"(r[0]), "=r"(r[1]), "=r"(r[2]), "=r"(r[3]) : "r"(addr));
}
__device__ __forceinline__ void mma_bf16(float* d, const uint32_t* a, uint32_t b0, uint32_t b1) {
    asm volatile(
        "mma.sync.aligned.m16n8k16.row.col.f32.bf16.bf16.f32 "
        "{%0,%1,%2,%3}, {%4,%5,%6,%7}, {%8,%9}, {%0,%1,%2,%3};"
        : "+f"(d[0]), "+f"(d[1]), "+f"(d[2]), "+f"(d[3])
        : "r"(a[0]), "r"(a[1]), "r"(a[2]), "r"(a[3]), "r"(b0), "r"(b1));
}

// ---------------- init ----------------
__global__ void zero_init_kernel() {
    int i = blockIdx.x * blockDim.x + threadIdx.x;
    if (i < NN * RR) d_cnt[i] = 0;
    if (i < NN) { d_deg[i] = 0; d_cursor[i] = 0; }
    if (i < GG * HH) d_pool[i] = 0.0f;
    if (i < GG) d_poolcnt[i] = 0.0f;
}

// ---------------- weight prep: transpose + hi/lo split ----------------
__global__ void wprep_kernel(const float* __restrict__ bases,
                             const float* __restrict__ root, int layer) {
    int i = blockIdx.x * blockDim.x + threadIdx.x;
    if (i >= KTOT * NTILE) return;
    int k = i >> 7, n = i & 127;
    float w = (k < 512) ? bases[k * 128 + n] : root[(k - 512) * 128 + n];
    __nv_bfloat16 h = __float2bfloat16(w);
    float hf = __bfloat162float(h);
    __nv_bfloat16 l = __float2bfloat16(w - hf);
    size_t o = (size_t)layer * NTILE * KTOT + (size_t)n * KTOT + k;
    d_wt_hi[o] = h;
    d_wt_lo[o] = l;
}

// ---------------- CSR build ----------------
__global__ void count_kernel(const int* __restrict__ ei, const int* __restrict__ et) {
    int e = blockIdx.x * blockDim.x + threadIdx.x;
    if (e >= EE) return;
    int dst = __ldg(ei + EE + e);
    int t   = __ldg(et + e);
    atomicAdd(&d_deg[dst], 1);
    atomicAdd(&d_cnt[dst * RR + t], 1);
}

__global__ void scan_kernel() {   // 1 block, 1024 threads
    const int T = 1024;
    __shared__ int sh[T];
    int tid = threadIdx.x;
    int chunk = (NN + T - 1) / T;
    int start = tid * chunk;
    int endi  = start + chunk; if (endi > NN) endi = NN;
    int s = 0;
    for (int i = start; i < endi && start < NN; i++) s += d_deg[i];
    sh[tid] = (start < NN) ? s : 0;
    __syncthreads();
    for (int off = 1; off < T; off <<= 1) {
        int v = (tid >= off) ? sh[tid - off] : 0;
        __syncthreads();
        if (tid >= off) sh[tid] += v;
        __syncthreads();
    }
    int run = (tid == 0) ? 0 : sh[tid - 1];
    if (start < NN) {
        for (int i = start; i < endi; i++) { d_rowptr[i] = run; run += d_deg[i]; }
    }
    if (tid == T - 1) d_rowptr[NN] = sh[T - 1];
}

__global__ void invcnt_kernel() {
    int i = blockIdx.x * blockDim.x + threadIdx.x;
    if (i >= NN * RR) return;
    int c = d_cnt[i];
    d_invcnt[i] = 1.0f / (float)(c > 1 ? c : 1);
}

__global__ void scatter_kernel(const int* __restrict__ ei, const int* __restrict__ et) {
    int e = blockIdx.x * blockDim.x + threadIdx.x;
    if (e >= EE) return;
    int src = __ldg(ei + e);
    int dst = __ldg(ei + EE + e);
    int t   = __ldg(et + e);
    int pos = d_rowptr[dst] + atomicAdd(&d_cursor[dst], 1);
    d_csr[pos] = (unsigned)src | ((unsigned)t << 20);
}

// ---------------- per-layer aggregation -> z[N,512] ----------------
__global__ void agg_kernel(int sel, const float* __restrict__ x0,
                           const float* __restrict__ comp /*[R,NB]*/) {
    __shared__ float s_comp[RR * NB];
    int tid = threadIdx.x;
    if (tid < RR * NB) s_comp[tid] = comp[tid];
    __syncthreads();

    int warp = (blockIdx.x * blockDim.x + tid) >> 5;
    int lane = tid & 31;
    if (warp >= NN) return;

    const float* X = (sel == 0) ? x0 : (sel == 1 ? d_h1 : d_h2);

    int beg = d_rowptr[warp];
    int end = d_rowptr[warp + 1];
    float inv_t = (lane < RR) ? d_invcnt[warp * RR + lane] : 0.0f;

    float4 acc0 = {0,0,0,0}, acc1 = {0,0,0,0}, acc2 = {0,0,0,0}, acc3 = {0,0,0,0};

    #pragma unroll 4
    for (int i = beg; i < end; i++) {
        unsigned p = d_csr[i];
        int src = (int)(p & 0xFFFFFu);
        int t   = (int)(p >> 20);
        float ic = __shfl_sync(0xffffffffu, inv_t, t);
        float4 v = *(const float4*)(X + (size_t)src * HH + lane * 4);
        float w0 = s_comp[t * NB + 0] * ic;
        float w1 = s_comp[t * NB + 1] * ic;
        float w2 = s_comp[t * NB + 2] * ic;
        float w3 = s_comp[t * NB + 3] * ic;
        acc0.x += w0 * v.x; acc0.y += w0 * v.y; acc0.z += w0 * v.z; acc0.w += w0 * v.w;
        acc1.x += w1 * v.x; acc1.y += w1 * v.y; acc1.z += w1 * v.z; acc1.w += w1 * v.w;
        acc2.x += w2 * v.x; acc2.y += w2 * v.y; acc2.z += w2 * v.z; acc2.w += w2 * v.w;
        acc3.x += w3 * v.x; acc3.y += w3 * v.y; acc3.z += w3 * v.z; acc3.w += w3 * v.w;
    }

    float* zp = d_z + (size_t)warp * 512 + lane * 4;
    *(float4*)(zp + 0 * HH) = acc0;
    *(float4*)(zp + 1 * HH) = acc1;
    *(float4*)(zp + 2 * HH) = acc2;
    *(float4*)(zp + 3 * HH) = acc3;
}

// ---------------- tensor-core GEMM via mma.sync (HMMA bf16, 3-term split) ------
// one CTA per 128-row tile, 256 threads (8 warps). Warp tile 64x32.
// SMEM (64KB): Ah[16K] Al[16K] Bh[16K] Bl[16K]; tiles [128 rows][64 k] bf16,
// row stride 128B, SW128 swizzle.
__global__ void __launch_bounds__(256, 1)
tc_gemm_kernel(int sel, const float* __restrict__ x0, int osel,
               const float* __restrict__ bias, int relu, int layer) {
    extern __shared__ __align__(1024) char smem[];
    uint32_t sb = smem_u32(smem);
    int tid = threadIdx.x;
    int wid = tid >> 5;
    int lane = tid & 31;
    int row0 = blockIdx.x * MTILE;

    const float* X = (sel == 0) ? x0 : (sel == 1 ? d_h1 : d_h2);
    float* OUT = (osel == 1) ? d_h1 : d_h2;
    const __nv_bfloat16* Whi = d_wt_hi + (size_t)layer * NTILE * KTOT;
    const __nv_bfloat16* Wlo = d_wt_lo + (size_t)layer * NTILE * KTOT;

    int wm = (wid & 1) * 64;          // warp row block
    int wn = (wid >> 1) * 32;         // warp col block

    // ldmatrix lane addressing components
    int sub = lane & 7, g = lane >> 3;
    int a_r = sub + ((g & 1) << 3);   // row within m16 tile
    int a_k = (g >> 1) << 3;          // k offset within k16
    int b_r = sub + ((g >> 1) << 3);  // row within n16 tile
    int b_k = (g & 1) << 3;           // k offset within k16

    float acc[4][4][4];
    #pragma unroll
    for (int mt = 0; mt < 4; mt++)
        #pragma unroll
        for (int nt = 0; nt < 4; nt++)
            #pragma unroll
            for (int q = 0; q < 4; q++) acc[mt][nt][q] = 0.0f;

    for (int c = 0; c < NCHUNKS; c++) {
        if (c) __syncthreads();

        // ---- A tile: 128 rows x 64 k fp32 -> bf16 hi/lo, SW128
        #pragma unroll
        for (int i = 0; i < 4; i++) {
            int gg = tid + i * 256;           // 0..1023: 128 rows x 8 col-groups
            int r = gg >> 3;
            int c8 = (gg & 7) * 8;
            int gm = row0 + r;
            float4 v0 = make_float4(0.f, 0.f, 0.f, 0.f), v1 = v0;
            if (gm < NN) {
                const float* src = (c < 8)
                    ? (d_z + (size_t)gm * 512 + c * KCHUNK + c8)
                    : (X + (size_t)gm * 128 + (c - 8) * KCHUNK + c8);
                v0 = *(const float4*)src;
                v1 = *(const float4*)(src + 4);
            }
            uint32_t h0, h1, h2, h3, l0, l1, l2, l3;
            split2(v0.x, v0.y, h0, l0); split2(v0.z, v0.w, h1, l1);
            split2(v1.x, v1.y, h2, l2); split2(v1.z, v1.w, h3, l3);
            uint32_t off = SW128((uint32_t)(r * 128 + c8 * 2));
            *(uint4*)(smem + off)         = make_uint4(h0, h1, h2, h3);
            *(uint4*)(smem + 16384 + off) = make_uint4(l0, l1, l2, l3);
        }
        // ---- B tile: W_t[n, c*64 .. +63] hi/lo bf16, SW128
        #pragma unroll
        for (int i = 0; i < 8; i++) {
            int gg = tid + i * 256;           // 0..2047
            int lohi = gg >> 10;              // 0=hi, 1=lo
            int g2 = gg & 1023;
            int r = g2 >> 3;
            int c8 = (g2 & 7) * 8;
            const __nv_bfloat16* src = (lohi ? Wlo : Whi) + (size_t)r * KTOT + c * KCHUNK + c8;
            uint4 v = *(const uint4*)src;
            *(uint4*)(smem + (lohi ? 49152 : 32768) + SW128((uint32_t)(r * 128 + c8 * 2))) = v;
        }
        __syncthreads();

        // ---- compute: 4 ksteps x (16 tiles x 3 terms)
        #pragma unroll
        for (int ks = 0; ks < 4; ks++) {
            uint32_t ah[4][4], al[4][4], bh[2][4], bl[2][4];
            #pragma unroll
            for (int mt = 0; mt < 4; mt++) {
                uint32_t off = SW128((uint32_t)((wm + mt * 16 + a_r) * 128 + (ks * 16 + a_k) * 2));
                ldsm_x4(ah[mt], sb + off);
                ldsm_x4(al[mt], sb + 16384 + off);
            }
            #pragma unroll
            for (int nt2 = 0; nt2 < 2; nt2++) {
                uint32_t off = SW128((uint32_t)((wn + nt2 * 16 + b_r) * 128 + (ks * 16 + b_k) * 2));
                ldsm_x4(bh[nt2], sb + 32768 + off);
                ldsm_x4(bl[nt2], sb + 49152 + off);
            }
            #pragma unroll
            for (int mt = 0; mt < 4; mt++)
                #pragma unroll
                for (int nt = 0; nt < 4; nt++) {
                    uint32_t b0h = bh[nt >> 1][(nt & 1) * 2], b1h = bh[nt >> 1][(nt & 1) * 2 + 1];
                    uint32_t b0l = bl[nt >> 1][(nt & 1) * 2], b1l = bl[nt >> 1][(nt & 1) * 2 + 1];
                    mma_bf16(acc[mt][nt], ah[mt], b0h, b1h);
                    mma_bf16(acc[mt][nt], ah[mt], b0l, b1l);
                    mma_bf16(acc[mt][nt], al[mt], b0h, b1h);
                }
        }
    }

    // ---- epilogue: c-frag layout m16n8: (c0,c1)->row lane/4, (c2,c3)->row+8
    #pragma unroll
    for (int mt = 0; mt < 4; mt++) {
        int r_lo = row0 + wm + mt * 16 + (lane >> 2);
        int r_hi = r_lo + 8;
        #pragma unroll
        for (int nt = 0; nt < 4; nt++) {
            int col = wn + nt * 8 + ((lane & 3) << 1);
            float2 b2 = *(const float2*)(bias + col);
            if (r_lo < NN) {
                float2 v;
                v.x = acc[mt][nt][0] + b2.x;
                v.y = acc[mt][nt][1] + b2.y;
                if (relu) { v.x = fmaxf(v.x, 0.f); v.y = fmaxf(v.y, 0.f); }
                *(float2*)(OUT + (size_t)r_lo * 128 + col) = v;
            }
            if (r_hi < NN) {
                float2 v;
                v.x = acc[mt][nt][2] + b2.x;
                v.y = acc[mt][nt][3] + b2.y;
                if (relu) { v.x = fmaxf(v.x, 0.f); v.y = fmaxf(v.y, 0.f); }
                *(float2*)(OUT + (size_t)r_hi * 128 + col) = v;
            }
        }
    }
}

// ---------------- pooling ----------------
__global__ void pool_kernel(const int* __restrict__ batch) {
    int warp = (blockIdx.x * blockDim.x + threadIdx.x) >> 5;
    int lane = threadIdx.x & 31;
    if (warp >= NN) return;
    int g = __ldg(batch + warp);
    float4 v = *(const float4*)(d_h1 + (size_t)warp * 128 + lane * 4);
    atomicAdd(&d_pool[g * 128 + lane * 4 + 0], v.x);
    atomicAdd(&d_pool[g * 128 + lane * 4 + 1], v.y);
    atomicAdd(&d_pool[g * 128 + lane * 4 + 2], v.z);
    atomicAdd(&d_pool[g * 128 + lane * 4 + 3], v.w);
    if (lane == 0) atomicAdd(&d_poolcnt[g], 1.0f);
}

__global__ void final_kernel(const int* __restrict__ rl,
                             const float* __restrict__ rel_emb,
                             const float* __restrict__ lw,   // [256,2]
                             const float* __restrict__ lb,   // [2]
                             float* __restrict__ out) {
    int t = threadIdx.x;
    if (t >= GG * NC) return;
    int g = t >> 1, c = t & 1;
    float cnt = d_poolcnt[g];
    float invc = 1.0f / (cnt > 1.0f ? cnt : 1.0f);
    const float* re = rel_emb + (size_t)rl[g] * 128;
    float s = 0.f;
    for (int j = 0; j < 128; j++) s += d_pool[g * 128 + j] * invc * lw[j * 2 + c];
    for (int j = 0; j < 128; j++) s += re[j] * lw[(128 + j) * 2 + c];
    out[g * 2 + c] = s + lb[c];
}

// ---------------- launch ----------------
extern "C" void kernel_launch(void* const* d_in, const int* in_sizes, int n_in,
                              void* d_out, int out_size) {
    const float* x      = (const float*)d_in[0];
    const int*   ei     = (const int*)d_in[1];
    const int*   et     = (const int*)d_in[2];
    const int*   batch  = (const int*)d_in[3];
    const int*   rl     = (const int*)d_in[4];
    const float* relemb = (const float*)d_in[6];
    const float* bases[3] = {(const float*)d_in[7],  (const float*)d_in[11], (const float*)d_in[15]};
    const float* comp[3]  = {(const float*)d_in[8],  (const float*)d_in[12], (const float*)d_in[16]};
    const float* root[3]  = {(const float*)d_in[9],  (const float*)d_in[13], (const float*)d_in[17]};
    const float* bias[3]  = {(const float*)d_in[10], (const float*)d_in[14], (const float*)d_in[18]};
    const float* lin_w  = (const float*)d_in[19];
    const float* lin_b  = (const float*)d_in[20];
    float* out = (float*)d_out;

    cudaFuncSetAttribute(tc_gemm_kernel, cudaFuncAttributeMaxDynamicSharedMemorySize, GEMM_SMEM);

    const int TB = 256;
    zero_init_kernel<<<(NN * RR + TB - 1) / TB, TB>>>();
    count_kernel<<<(EE + TB - 1) / TB, TB>>>(ei, et);
    scan_kernel<<<1, 1024>>>();
    invcnt_kernel<<<(NN * RR + TB - 1) / TB, TB>>>();
    scatter_kernel<<<(EE + TB - 1) / TB, TB>>>(ei, et);

    int wpBlocks = (KTOT * NTILE + TB - 1) / TB;
    wprep_kernel<<<wpBlocks, TB>>>(bases[0], root[0], 0);
    wprep_kernel<<<wpBlocks, TB>>>(bases[1], root[1], 1);
    wprep_kernel<<<wpBlocks, TB>>>(bases[2], root[2], 2);

    int aggBlocks = (NN * 32 + TB - 1) / TB;

    // layer 1: in = x, out = h1, relu
    agg_kernel<<<aggBlocks, TB>>>(0, x, comp[0]);
    tc_gemm_kernel<<<GEMM_GRID, 256, GEMM_SMEM>>>(0, x, 1, bias[0], 1, 0);
    // layer 2: in = h1, out = h2, relu
    agg_kernel<<<aggBlocks, TB>>>(1, x, comp[1]);
    tc_gemm_kernel<<<GEMM_GRID, 256, GEMM_SMEM>>>(1, x, 2, bias[1], 1, 1);
    // layer 3: in = h2, out = h1, no relu
    agg_kernel<<<aggBlocks, TB>>>(2, x, comp[2]);
    tc_gemm_kernel<<<GEMM_GRID, 256, GEMM_SMEM>>>(2, x, 1, bias[2], 0, 2);

    pool_kernel<<<aggBlocks, TB>>>(batch);
    final_kernel<<<1, 128>>>(rl, relemb, lin_w, lin_b, out);
}

// round 7
// speedup vs baseline: 1.6323x; 1.1159x over previous
#include <cuda_runtime.h>
#include <cuda_bf16.h>
#include <cstdint>

// Problem constants
#define NN   50000
#define NPAD 50048
#define EE   1600000
#define RR   16
#define NB   4
#define HH   128
#define GG   64
#define NC   2

#define KTOT 640
#define MTILE 128
#define NTILE 128
#define KCHUNK 64
#define NCHUNKS 10
#define GEMM_GRID ((NN + MTILE - 1) / MTILE)   // 391
#define STAGE_BYTES 65536
#define GEMM_SMEM (2 * STAGE_BYTES)

// ---------------- device scratch (static, no allocs) ----------------
__device__ unsigned int d_csr[EE];
__device__ int   d_rowptr[NN + 1];
__device__ int   d_deg[NN];
__device__ int   d_cursor[NN];
__device__ int   d_cnt[NN * RR];
__device__ float d_invcnt[NN * RR];
__device__ float d_h1[(size_t)NN * HH];
__device__ float d_h2[(size_t)NN * HH];
__device__ float d_pool[GG * HH];
__device__ float d_poolcnt[GG];
// pre-split bf16 operands (padded rows)
__device__ __nv_bfloat16 d_z_hi[(size_t)NPAD * 512];
__device__ __nv_bfloat16 d_z_lo[(size_t)NPAD * 512];
__device__ __nv_bfloat16 d_x_hi[(size_t)NPAD * HH];
__device__ __nv_bfloat16 d_x_lo[(size_t)NPAD * HH];
__device__ __nv_bfloat16 d_h1_hi[(size_t)NPAD * HH];
__device__ __nv_bfloat16 d_h1_lo[(size_t)NPAD * HH];
__device__ __nv_bfloat16 d_h2_hi[(size_t)NPAD * HH];
__device__ __nv_bfloat16 d_h2_lo[(size_t)NPAD * HH];
// transposed + hi/lo split weights: [layer][n(128)][k(640)]
__device__ __nv_bfloat16 d_wt_hi[3 * NTILE * KTOT];
__device__ __nv_bfloat16 d_wt_lo[3 * NTILE * KTOT];

// ---------------- helpers ----------------
__device__ __forceinline__ uint32_t smem_u32(const void* p) {
    uint32_t a;
    asm("{ .reg .u64 t; cvta.to.shared.u64 t, %1; cvt.u32.u64 %0, t; }" : "=r"(a) : "l"(p));
    return a;
}
#define SW128(o) ((o) ^ (((o) >> 3) & 0x70))

__device__ __forceinline__ void split2(float a, float b, uint32_t& hi, uint32_t& lo) {
    __nv_bfloat16 ha = __float2bfloat16(a), hb = __float2bfloat16(b);
    float fa = __bfloat162float(ha), fb = __bfloat162float(hb);
    __nv_bfloat16 la = __float2bfloat16(a - fa), lb = __float2bfloat16(b - fb);
    hi = (uint32_t)__bfloat16_as_ushort(ha) | ((uint32_t)__bfloat16_as_ushort(hb) << 16);
    lo = (uint32_t)__bfloat16_as_ushort(la) | ((uint32_t)__bfloat16_as_ushort(lb) << 16);
}

__device__ __forceinline__ void ldsm_x4(uint32_t* r, uint32_t addr) {
    asm volatile("ldmatrix.sync.aligned.m8n8.x4.shared.b16 {%0,%1,%2,%3}, [%4];"
                 : "=r"(r[0]), "=r"(r[1]), "=r"(r[2]), "=r"(r[3]) : "r"(addr));
}
__device__ __forceinline__ void mma_bf16(float* d, const uint32_t* a, uint32_t b0, uint32_t b1) {
    asm volatile(
        "mma.sync.aligned.m16n8k16.row.col.f32.bf16.bf16.f32 "
        "{%0,%1,%2,%3}, {%4,%5,%6,%7}, {%8,%9}, {%0,%1,%2,%3};"
        : "+f"(d[0]), "+f"(d[1]), "+f"(d[2]), "+f"(d[3])
        : "r"(a[0]), "r"(a[1]), "r"(a[2]), "r"(a[3]), "r"(b0), "r"(b1));
}
__device__ __forceinline__ void cp16(uint32_t smem_dst, const void* gsrc) {
    asm volatile("cp.async.cg.shared.global [%0], [%1], 16;" :: "r"(smem_dst), "l"(gsrc));
}
__device__ __forceinline__ void cp_commit() {
    asm volatile("cp.async.commit_group;" ::: "memory");
}
template<int N> __device__ __forceinline__ void cp_wait() {
    asm volatile("cp.async.wait_group %0;" :: "n"(N) : "memory");
}

// ---------------- init ----------------
__global__ void zero_init_kernel() {
    int i = blockIdx.x * blockDim.x + threadIdx.x;
    if (i < NN * RR) d_cnt[i] = 0;
    if (i < NN) { d_deg[i] = 0; d_cursor[i] = 0; }
    if (i < GG * HH) d_pool[i] = 0.0f;
    if (i < GG) d_poolcnt[i] = 0.0f;
}

// ---------------- one-time x split ----------------
__global__ void xsplit_kernel(const float* __restrict__ x) {
    int i = blockIdx.x * blockDim.x + threadIdx.x;
    if (i >= NN * HH / 2) return;
    float2 v = *(const float2*)(x + i * 2);
    uint32_t h, l;
    split2(v.x, v.y, h, l);
    *(uint32_t*)((__nv_bfloat16*)d_x_hi + (size_t)i * 2) = h;
    *(uint32_t*)((__nv_bfloat16*)d_x_lo + (size_t)i * 2) = l;
}

// ---------------- weight prep: transpose + hi/lo split ----------------
__global__ void wprep_kernel(const float* __restrict__ bases,
                             const float* __restrict__ root, int layer) {
    int i = blockIdx.x * blockDim.x + threadIdx.x;
    if (i >= KTOT * NTILE) return;
    int k = i >> 7, n = i & 127;
    float w = (k < 512) ? bases[k * 128 + n] : root[(k - 512) * 128 + n];
    __nv_bfloat16 h = __float2bfloat16(w);
    float hf = __bfloat162float(h);
    __nv_bfloat16 l = __float2bfloat16(w - hf);
    size_t o = (size_t)layer * NTILE * KTOT + (size_t)n * KTOT + k;
    d_wt_hi[o] = h;
    d_wt_lo[o] = l;
}

// ---------------- CSR build ----------------
__global__ void count_kernel(const int* __restrict__ ei, const int* __restrict__ et) {
    int e = blockIdx.x * blockDim.x + threadIdx.x;
    if (e >= EE) return;
    int dst = __ldg(ei + EE + e);
    int t   = __ldg(et + e);
    atomicAdd(&d_deg[dst], 1);
    atomicAdd(&d_cnt[dst * RR + t], 1);
}

__global__ void scan_kernel() {   // 1 block, 1024 threads
    const int T = 1024;
    __shared__ int sh[T];
    int tid = threadIdx.x;
    int chunk = (NN + T - 1) / T;
    int start = tid * chunk;
    int endi  = start + chunk; if (endi > NN) endi = NN;
    int s = 0;
    for (int i = start; i < endi && start < NN; i++) s += d_deg[i];
    sh[tid] = (start < NN) ? s : 0;
    __syncthreads();
    for (int off = 1; off < T; off <<= 1) {
        int v = (tid >= off) ? sh[tid - off] : 0;
        __syncthreads();
        if (tid >= off) sh[tid] += v;
        __syncthreads();
    }
    int run = (tid == 0) ? 0 : sh[tid - 1];
    if (start < NN) {
        for (int i = start; i < endi; i++) { d_rowptr[i] = run; run += d_deg[i]; }
    }
    if (tid == T - 1) d_rowptr[NN] = sh[T - 1];
}

__global__ void invcnt_kernel() {
    int i = blockIdx.x * blockDim.x + threadIdx.x;
    if (i >= NN * RR) return;
    int c = d_cnt[i];
    d_invcnt[i] = 1.0f / (float)(c > 1 ? c : 1);
}

__global__ void scatter_kernel(const int* __restrict__ ei, const int* __restrict__ et) {
    int e = blockIdx.x * blockDim.x + threadIdx.x;
    if (e >= EE) return;
    int src = __ldg(ei + e);
    int dst = __ldg(ei + EE + e);
    int t   = __ldg(et + e);
    int pos = d_rowptr[dst] + atomicAdd(&d_cursor[dst], 1);
    d_csr[pos] = (unsigned)src | ((unsigned)t << 20);
}

// ---------------- per-layer aggregation -> z_hi/z_lo [N,512] bf16 --------------
__global__ void agg_kernel(int sel, const float* __restrict__ x0,
                           const float* __restrict__ comp /*[R,NB]*/) {
    __shared__ float s_comp[RR * NB];
    int tid = threadIdx.x;
    if (tid < RR * NB) s_comp[tid] = comp[tid];
    __syncthreads();

    int warp = (blockIdx.x * blockDim.x + tid) >> 5;
    int lane = tid & 31;
    if (warp >= NN) return;

    const float* X = (sel == 0) ? x0 : (sel == 1 ? d_h1 : d_h2);

    int beg = d_rowptr[warp];
    int end = d_rowptr[warp + 1];
    float inv_t = (lane < RR) ? d_invcnt[warp * RR + lane] : 0.0f;

    float4 acc[NB];
    #pragma unroll
    for (int b = 0; b < NB; b++) acc[b] = make_float4(0.f, 0.f, 0.f, 0.f);

    #pragma unroll 4
    for (int i = beg; i < end; i++) {
        unsigned p = d_csr[i];
        int src = (int)(p & 0xFFFFFu);
        int t   = (int)(p >> 20);
        float ic = __shfl_sync(0xffffffffu, inv_t, t);
        float4 v = *(const float4*)(X + (size_t)src * HH + lane * 4);
        #pragma unroll
        for (int b = 0; b < NB; b++) {
            float w = s_comp[t * NB + b] * ic;
            acc[b].x += w * v.x; acc[b].y += w * v.y;
            acc[b].z += w * v.z; acc[b].w += w * v.w;
        }
    }

    size_t base = (size_t)warp * 512 + lane * 4;
    #pragma unroll
    for (int b = 0; b < NB; b++) {
        uint32_t h0, h1, l0, l1;
        split2(acc[b].x, acc[b].y, h0, l0);
        split2(acc[b].z, acc[b].w, h1, l1);
        *(uint2*)(d_z_hi + base + b * 128) = make_uint2(h0, h1);
        *(uint2*)(d_z_lo + base + b * 128) = make_uint2(l0, l1);
    }
}

// ---------------- tensor-core GEMM: cp.async double-buffered HMMA --------------
// stage layout: Ah[16K] Al[16K] Bh[16K] Bl[16K]; tiles [128 rows][64 k] bf16,
// row stride 128B, SW128 swizzle.
__global__ void __launch_bounds__(256, 1)
tc_gemm_kernel(const __nv_bfloat16* __restrict__ Xhi, const __nv_bfloat16* __restrict__ Xlo,
               float* __restrict__ OUT,
               __nv_bfloat16* __restrict__ OUThi, __nv_bfloat16* __restrict__ OUTlo,
               const float* __restrict__ bias, int relu, int layer) {
    extern __shared__ __align__(1024) char smem[];
    uint32_t sb = smem_u32(smem);
    int tid = threadIdx.x;
    int wid = tid >> 5;
    int lane = tid & 31;
    int row0 = blockIdx.x * MTILE;

    const __nv_bfloat16* Whi = d_wt_hi + (size_t)layer * NTILE * KTOT;
    const __nv_bfloat16* Wlo = d_wt_lo + (size_t)layer * NTILE * KTOT;

    // per-thread load coordinates: 4 positions of the 1024 (row, col8) pairs
    int lr[4], lc[4];
    uint32_t ldst[4];
    #pragma unroll
    for (int i = 0; i < 4; i++) {
        int g = tid + i * 256;
        lr[i] = g >> 3;
        lc[i] = (g & 7) * 8;
        ldst[i] = SW128((uint32_t)(lr[i] * 128 + lc[i] * 2));
    }

    // ---- loader lambda-ish macro
    #define LOAD_CHUNK(c, stage)                                                      \
    {                                                                                 \
        uint32_t s0 = sb + (stage) * STAGE_BYTES;                                     \
        _Pragma("unroll")                                                             \
        for (int i = 0; i < 4; i++) {                                                 \
            int gm = row0 + lr[i];                                                    \
            const __nv_bfloat16 *ah, *al;                                             \
            if ((c) < 8) {                                                            \
                ah = d_z_hi + (size_t)gm * 512 + (c) * KCHUNK + lc[i];                \
                al = d_z_lo + (size_t)gm * 512 + (c) * KCHUNK + lc[i];                \
            } else {                                                                  \
                ah = Xhi + (size_t)gm * 128 + ((c) - 8) * KCHUNK + lc[i];             \
                al = Xlo + (size_t)gm * 128 + ((c) - 8) * KCHUNK + lc[i];             \
            }                                                                         \
            cp16(s0 + ldst[i], ah);                                                   \
            cp16(s0 + 16384 + ldst[i], al);                                           \
            const __nv_bfloat16* bh = Whi + (size_t)lr[i] * KTOT + (c) * KCHUNK + lc[i]; \
            const __nv_bfloat16* bl = Wlo + (size_t)lr[i] * KTOT + (c) * KCHUNK + lc[i]; \
            cp16(s0 + 32768 + ldst[i], bh);                                           \
            cp16(s0 + 49152 + ldst[i], bl);                                           \
        }                                                                             \
    }

    int wm = (wid & 1) * 64;
    int wn = (wid >> 1) * 32;

    int sub = lane & 7, g = lane >> 3;
    int a_r = sub + ((g & 1) << 3);
    int a_k = (g >> 1) << 3;
    int b_r = sub + ((g >> 1) << 3);
    int b_k = (g & 1) << 3;

    float acc[4][4][4];
    #pragma unroll
    for (int mt = 0; mt < 4; mt++)
        #pragma unroll
        for (int nt = 0; nt < 4; nt++)
            #pragma unroll
            for (int q = 0; q < 4; q++) acc[mt][nt][q] = 0.0f;

    LOAD_CHUNK(0, 0);
    cp_commit();

    for (int c = 0; c < NCHUNKS; c++) {
        if (c + 1 < NCHUNKS) {
            LOAD_CHUNK(c + 1, (c + 1) & 1);
            cp_commit();
            cp_wait<1>();
        } else {
            cp_wait<0>();
        }
        __syncthreads();

        uint32_t s0 = sb + (c & 1) * STAGE_BYTES;
        #pragma unroll
        for (int ks = 0; ks < 4; ks++) {
            uint32_t ah[4][4], al[4][4], bh[2][4], bl[2][4];
            #pragma unroll
            for (int mt = 0; mt < 4; mt++) {
                uint32_t off = SW128((uint32_t)((wm + mt * 16 + a_r) * 128 + (ks * 16 + a_k) * 2));
                ldsm_x4(ah[mt], s0 + off);
                ldsm_x4(al[mt], s0 + 16384 + off);
            }
            #pragma unroll
            for (int nt2 = 0; nt2 < 2; nt2++) {
                uint32_t off = SW128((uint32_t)((wn + nt2 * 16 + b_r) * 128 + (ks * 16 + b_k) * 2));
                ldsm_x4(bh[nt2], s0 + 32768 + off);
                ldsm_x4(bl[nt2], s0 + 49152 + off);
            }
            #pragma unroll
            for (int mt = 0; mt < 4; mt++)
                #pragma unroll
                for (int nt = 0; nt < 4; nt++) {
                    uint32_t b0h = bh[nt >> 1][(nt & 1) * 2], b1h = bh[nt >> 1][(nt & 1) * 2 + 1];
                    uint32_t b0l = bl[nt >> 1][(nt & 1) * 2], b1l = bl[nt >> 1][(nt & 1) * 2 + 1];
                    mma_bf16(acc[mt][nt], ah[mt], b0h, b1h);
                    mma_bf16(acc[mt][nt], ah[mt], b0l, b1l);
                    mma_bf16(acc[mt][nt], al[mt], b0h, b1h);
                }
        }
        __syncthreads();
    }
    #undef LOAD_CHUNK

    // ---- epilogue
    #pragma unroll
    for (int mt = 0; mt < 4; mt++) {
        int r_lo = row0 + wm + mt * 16 + (lane >> 2);
        int r_hi = r_lo + 8;
        #pragma unroll
        for (int nt = 0; nt < 4; nt++) {
            int col = wn + nt * 8 + ((lane & 3) << 1);
            float2 b2 = *(const float2*)(bias + col);
            if (r_lo < NN) {
                float2 v;
                v.x = acc[mt][nt][0] + b2.x;
                v.y = acc[mt][nt][1] + b2.y;
                if (relu) { v.x = fmaxf(v.x, 0.f); v.y = fmaxf(v.y, 0.f); }
                *(float2*)(OUT + (size_t)r_lo * 128 + col) = v;
                if (OUThi) {
                    uint32_t h, l;
                    split2(v.x, v.y, h, l);
                    *(uint32_t*)(OUThi + (size_t)r_lo * 128 + col) = h;
                    *(uint32_t*)(OUTlo + (size_t)r_lo * 128 + col) = l;
                }
            }
            if (r_hi < NN) {
                float2 v;
                v.x = acc[mt][nt][2] + b2.x;
                v.y = acc[mt][nt][3] + b2.y;
                if (relu) { v.x = fmaxf(v.x, 0.f); v.y = fmaxf(v.y, 0.f); }
                *(float2*)(OUT + (size_t)r_hi * 128 + col) = v;
                if (OUThi) {
                    uint32_t h, l;
                    split2(v.x, v.y, h, l);
                    *(uint32_t*)(OUThi + (size_t)r_hi * 128 + col) = h;
                    *(uint32_t*)(OUTlo + (size_t)r_hi * 128 + col) = l;
                }
            }
        }
    }
}

// ---------------- pooling ----------------
__global__ void pool_kernel(const int* __restrict__ batch) {
    int warp = (blockIdx.x * blockDim.x + threadIdx.x) >> 5;
    int lane = threadIdx.x & 31;
    if (warp >= NN) return;
    int g = __ldg(batch + warp);
    float4 v = *(const float4*)(d_h1 + (size_t)warp * 128 + lane * 4);
    atomicAdd(&d_pool[g * 128 + lane * 4 + 0], v.x);
    atomicAdd(&d_pool[g * 128 + lane * 4 + 1], v.y);
    atomicAdd(&d_pool[g * 128 + lane * 4 + 2], v.z);
    atomicAdd(&d_pool[g * 128 + lane * 4 + 3], v.w);
    if (lane == 0) atomicAdd(&d_poolcnt[g], 1.0f);
}

__global__ void final_kernel(const int* __restrict__ rl,
                             const float* __restrict__ rel_emb,
                             const float* __restrict__ lw,   // [256,2]
                             const float* __restrict__ lb,   // [2]
                             float* __restrict__ out) {
    int t = threadIdx.x;
    if (t >= GG * NC) return;
    int g = t >> 1, c = t & 1;
    float cnt = d_poolcnt[g];
    float invc = 1.0f / (cnt > 1.0f ? cnt : 1.0f);
    const float* re = rel_emb + (size_t)rl[g] * 128;
    float s = 0.f;
    for (int j = 0; j < 128; j++) s += d_pool[g * 128 + j] * invc * lw[j * 2 + c];
    for (int j = 0; j < 128; j++) s += re[j] * lw[(128 + j) * 2 + c];
    out[g * 2 + c] = s + lb[c];
}

// ---------------- launch ----------------
extern "C" void kernel_launch(void* const* d_in, const int* in_sizes, int n_in,
                              void* d_out, int out_size) {
    const float* x      = (const float*)d_in[0];
    const int*   ei     = (const int*)d_in[1];
    const int*   et     = (const int*)d_in[2];
    const int*   batch  = (const int*)d_in[3];
    const int*   rl     = (const int*)d_in[4];
    const float* relemb = (const float*)d_in[6];
    const float* bases[3] = {(const float*)d_in[7],  (const float*)d_in[11], (const float*)d_in[15]};
    const float* comp[3]  = {(const float*)d_in[8],  (const float*)d_in[12], (const float*)d_in[16]};
    const float* root[3]  = {(const float*)d_in[9],  (const float*)d_in[13], (const float*)d_in[17]};
    const float* bias[3]  = {(const float*)d_in[10], (const float*)d_in[14], (const float*)d_in[18]};
    const float* lin_w  = (const float*)d_in[19];
    const float* lin_b  = (const float*)d_in[20];
    float* out = (float*)d_out;

    cudaFuncSetAttribute(tc_gemm_kernel, cudaFuncAttributeMaxDynamicSharedMemorySize, GEMM_SMEM);

    // resolve device symbol addresses for kernel params
    void* p_h1; void* p_h2;
    void* p_xh; void* p_xl; void* p_h1h; void* p_h1l; void* p_h2h; void* p_h2l;
    cudaGetSymbolAddress(&p_h1, d_h1);
    cudaGetSymbolAddress(&p_h2, d_h2);
    cudaGetSymbolAddress(&p_xh, d_x_hi);
    cudaGetSymbolAddress(&p_xl, d_x_lo);
    cudaGetSymbolAddress(&p_h1h, d_h1_hi);
    cudaGetSymbolAddress(&p_h1l, d_h1_lo);
    cudaGetSymbolAddress(&p_h2h, d_h2_hi);
    cudaGetSymbolAddress(&p_h2l, d_h2_lo);

    const int TB = 256;
    zero_init_kernel<<<(NN * RR + TB - 1) / TB, TB>>>();
    count_kernel<<<(EE + TB - 1) / TB, TB>>>(ei, et);
    scan_kernel<<<1, 1024>>>();
    invcnt_kernel<<<(NN * RR + TB - 1) / TB, TB>>>();
    scatter_kernel<<<(EE + TB - 1) / TB, TB>>>(ei, et);
    xsplit_kernel<<<(NN * HH / 2 + TB - 1) / TB, TB>>>(x);

    int wpBlocks = (KTOT * NTILE + TB - 1) / TB;
    wprep_kernel<<<wpBlocks, TB>>>(bases[0], root[0], 0);
    wprep_kernel<<<wpBlocks, TB>>>(bases[1], root[1], 1);
    wprep_kernel<<<wpBlocks, TB>>>(bases[2], root[2], 2);

    int aggBlocks = (NN * 32 + TB - 1) / TB;

    // layer 1: in = x, out = h1 (+bf16), relu
    agg_kernel<<<aggBlocks, TB>>>(0, x, comp[0]);
    tc_gemm_kernel<<<GEMM_GRID, 256, GEMM_SMEM>>>(
        (const __nv_bfloat16*)p_xh, (const __nv_bfloat16*)p_xl,
        (float*)p_h1, (__nv_bfloat16*)p_h1h, (__nv_bfloat16*)p_h1l, bias[0], 1, 0);
    // layer 2: in = h1, out = h2 (+bf16), relu
    agg_kernel<<<aggBlocks, TB>>>(1, x, comp[1]);
    tc_gemm_kernel<<<GEMM_GRID, 256, GEMM_SMEM>>>(
        (const __nv_bfloat16*)p_h1h, (const __nv_bfloat16*)p_h1l,
        (float*)p_h2, (__nv_bfloat16*)p_h2h, (__nv_bfloat16*)p_h2l, bias[1], 1, 1);
    // layer 3: in = h2, out = h1 (fp32 only), no relu
    agg_kernel<<<aggBlocks, TB>>>(2, x, comp[2]);
    tc_gemm_kernel<<<GEMM_GRID, 256, GEMM_SMEM>>>(
        (const __nv_bfloat16*)p_h2h, (const __nv_bfloat16*)p_h2l,
        (float*)p_h1, (__nv_bfloat16*)nullptr, (__nv_bfloat16*)nullptr, bias[2], 0, 2);

    pool_kernel<<<aggBlocks, TB>>>(batch);
    final_kernel<<<1, 128>>>(rl, relemb, lin_w, lin_b, out);
}

// round 8
// speedup vs baseline: 1.6814x; 1.0300x over previous
#include <cuda_runtime.h>
#include <cuda_bf16.h>
#include <cuda_fp16.h>
#include <cstdint>

// Problem constants
#define NN   50000
#define NPAD 50048
#define EE   1600000
#define RR   16
#define NB   4
#define HH   128
#define GG   64
#define NC   2

#define KTOT 640
#define MTILE 128
#define NTILE 128
#define KCHUNK 64
#define NCHUNKS 10
#define GEMM_GRID ((NN + MTILE - 1) / MTILE)   // 391
#define STAGE_BYTES 65536
#define GEMM_SMEM (2 * STAGE_BYTES)

// ---------------- device scratch (static, no allocs) ----------------
__device__ unsigned int d_csr[EE];
__device__ int   d_rowptr[NN + 1];
__device__ int   d_deg[NN];
__device__ int   d_cursor[NN];
__device__ int   d_cnt[NN * RR];
__device__ float d_invcnt[NN * RR];
__device__ float d_h1[(size_t)NN * HH];       // fp32 out of layer 3 (for pooling)
__device__ float d_pool[GG * HH];
__device__ float d_poolcnt[GG];
// fp16 gather mirrors
__device__ __half d_x16[(size_t)NPAD * HH];
__device__ __half d_h1_16[(size_t)NPAD * HH];
__device__ __half d_h2_16[(size_t)NPAD * HH];
// pre-split bf16 operands (padded rows)
__device__ __nv_bfloat16 d_z_hi[(size_t)NPAD * 512];
__device__ __nv_bfloat16 d_z_lo[(size_t)NPAD * 512];
__device__ __nv_bfloat16 d_x_hi[(size_t)NPAD * HH];
__device__ __nv_bfloat16 d_x_lo[(size_t)NPAD * HH];
__device__ __nv_bfloat16 d_h1_hi[(size_t)NPAD * HH];
__device__ __nv_bfloat16 d_h1_lo[(size_t)NPAD * HH];
__device__ __nv_bfloat16 d_h2_hi[(size_t)NPAD * HH];
__device__ __nv_bfloat16 d_h2_lo[(size_t)NPAD * HH];
// transposed + hi/lo split weights: [layer][n(128)][k(640)]
__device__ __nv_bfloat16 d_wt_hi[3 * NTILE * KTOT];
__device__ __nv_bfloat16 d_wt_lo[3 * NTILE * KTOT];

// ---------------- helpers ----------------
__device__ __forceinline__ uint32_t smem_u32(const void* p) {
    uint32_t a;
    asm("{ .reg .u64 t; cvta.to.shared.u64 t, %1; cvt.u32.u64 %0, t; }" : "=r"(a) : "l"(p));
    return a;
}
#define SW128(o) ((o) ^ (((o) >> 3) & 0x70))

__device__ __forceinline__ void split2(float a, float b, uint32_t& hi, uint32_t& lo) {
    __nv_bfloat16 ha = __float2bfloat16(a), hb = __float2bfloat16(b);
    float fa = __bfloat162float(ha), fb = __bfloat162float(hb);
    __nv_bfloat16 la = __float2bfloat16(a - fa), lb = __float2bfloat16(b - fb);
    hi = (uint32_t)__bfloat16_as_ushort(ha) | ((uint32_t)__bfloat16_as_ushort(hb) << 16);
    lo = (uint32_t)__bfloat16_as_ushort(la) | ((uint32_t)__bfloat16_as_ushort(lb) << 16);
}

__device__ __forceinline__ void ldsm_x4(uint32_t* r, uint32_t addr) {
    asm volatile("ldmatrix.sync.aligned.m8n8.x4.shared.b16 {%0,%1,%2,%3}, [%4];"
                 : "=r"(r[0]), "=r"(r[1]), "=r"(r[2]), "=r"(r[3]) : "r"(addr));
}
__device__ __forceinline__ void mma_bf16(float* d, const uint32_t* a, uint32_t b0, uint32_t b1) {
    asm volatile(
        "mma.sync.aligned.m16n8k16.row.col.f32.bf16.bf16.f32 "
        "{%0,%1,%2,%3}, {%4,%5,%6,%7}, {%8,%9}, {%0,%1,%2,%3};"
        : "+f"(d[0]), "+f"(d[1]), "+f"(d[2]), "+f"(d[3])
        : "r"(a[0]), "r"(a[1]), "r"(a[2]), "r"(a[3]), "r"(b0), "r"(b1));
}
__device__ __forceinline__ void cp16(uint32_t smem_dst, const void* gsrc) {
    asm volatile("cp.async.cg.shared.global [%0], [%1], 16;" :: "r"(smem_dst), "l"(gsrc));
}
__device__ __forceinline__ void cp_commit() {
    asm volatile("cp.async.commit_group;" ::: "memory");
}
template<int N> __device__ __forceinline__ void cp_wait() {
    asm volatile("cp.async.wait_group %0;" :: "n"(N) : "memory");
}

// ---------------- init ----------------
__global__ void zero_init_kernel() {
    int i = blockIdx.x * blockDim.x + threadIdx.x;
    if (i < NN * RR) d_cnt[i] = 0;
    if (i < NN) { d_deg[i] = 0; d_cursor[i] = 0; }
    if (i < GG * HH) d_pool[i] = 0.0f;
    if (i < GG) d_poolcnt[i] = 0.0f;
}

// ---------------- one-time x split: fp32 -> bf16 hi/lo + fp16 ----------------
__global__ void xsplit_kernel(const float* __restrict__ x) {
    int i = blockIdx.x * blockDim.x + threadIdx.x;
    if (i >= NN * HH / 2) return;
    float2 v = *(const float2*)(x + i * 2);
    uint32_t h, l;
    split2(v.x, v.y, h, l);
    *(uint32_t*)((__nv_bfloat16*)d_x_hi + (size_t)i * 2) = h;
    *(uint32_t*)((__nv_bfloat16*)d_x_lo + (size_t)i * 2) = l;
    __half2 p = __float22half2_rn(v);
    *(__half2*)(d_x16 + (size_t)i * 2) = p;
}

// ---------------- weight prep: transpose + hi/lo split ----------------
__global__ void wprep_kernel(const float* __restrict__ bases,
                             const float* __restrict__ root, int layer) {
    int i = blockIdx.x * blockDim.x + threadIdx.x;
    if (i >= KTOT * NTILE) return;
    int k = i >> 7, n = i & 127;
    float w = (k < 512) ? bases[k * 128 + n] : root[(k - 512) * 128 + n];
    __nv_bfloat16 h = __float2bfloat16(w);
    float hf = __bfloat162float(h);
    __nv_bfloat16 l = __float2bfloat16(w - hf);
    size_t o = (size_t)layer * NTILE * KTOT + (size_t)n * KTOT + k;
    d_wt_hi[o] = h;
    d_wt_lo[o] = l;
}

// ---------------- CSR build ----------------
__global__ void count_kernel(const int* __restrict__ ei, const int* __restrict__ et) {
    int e = blockIdx.x * blockDim.x + threadIdx.x;
    if (e >= EE) return;
    int dst = __ldg(ei + EE + e);
    int t   = __ldg(et + e);
    atomicAdd(&d_deg[dst], 1);
    atomicAdd(&d_cnt[dst * RR + t], 1);
}

__global__ void scan_kernel() {   // 1 block, 1024 threads
    const int T = 1024;
    __shared__ int sh[T];
    int tid = threadIdx.x;
    int chunk = (NN + T - 1) / T;
    int start = tid * chunk;
    int endi  = start + chunk; if (endi > NN) endi = NN;
    int s = 0;
    for (int i = start; i < endi && start < NN; i++) s += d_deg[i];
    sh[tid] = (start < NN) ? s : 0;
    __syncthreads();
    for (int off = 1; off < T; off <<= 1) {
        int v = (tid >= off) ? sh[tid - off] : 0;
        __syncthreads();
        if (tid >= off) sh[tid] += v;
        __syncthreads();
    }
    int run = (tid == 0) ? 0 : sh[tid - 1];
    if (start < NN) {
        for (int i = start; i < endi; i++) { d_rowptr[i] = run; run += d_deg[i]; }
    }
    if (tid == T - 1) d_rowptr[NN] = sh[T - 1];
}

__global__ void invcnt_kernel() {
    int i = blockIdx.x * blockDim.x + threadIdx.x;
    if (i >= NN * RR) return;
    int c = d_cnt[i];
    d_invcnt[i] = 1.0f / (float)(c > 1 ? c : 1);
}

__global__ void scatter_kernel(const int* __restrict__ ei, const int* __restrict__ et) {
    int e = blockIdx.x * blockDim.x + threadIdx.x;
    if (e >= EE) return;
    int src = __ldg(ei + e);
    int dst = __ldg(ei + EE + e);
    int t   = __ldg(et + e);
    int pos = d_rowptr[dst] + atomicAdd(&d_cursor[dst], 1);
    d_csr[pos] = (unsigned)src | ((unsigned)t << 20);
}

// ---------------- per-layer aggregation (fp16 gather) -> z_hi/z_lo bf16 -------
__global__ void agg_kernel(const __half* __restrict__ X16,
                           const float* __restrict__ comp /*[R,NB]*/) {
    __shared__ float s_comp[RR * NB];
    int tid = threadIdx.x;
    if (tid < RR * NB) s_comp[tid] = comp[tid];
    __syncthreads();

    int warp = (blockIdx.x * blockDim.x + tid) >> 5;
    int lane = tid & 31;
    if (warp >= NN) return;

    int beg = d_rowptr[warp];
    int end = d_rowptr[warp + 1];
    float inv_t = (lane < RR) ? d_invcnt[warp * RR + lane] : 0.0f;

    float4 acc[NB];
    #pragma unroll
    for (int b = 0; b < NB; b++) acc[b] = make_float4(0.f, 0.f, 0.f, 0.f);

    #pragma unroll 4
    for (int i = beg; i < end; i++) {
        unsigned p = d_csr[i];
        int src = (int)(p & 0xFFFFFu);
        int t   = (int)(p >> 20);
        float ic = __shfl_sync(0xffffffffu, inv_t, t);
        uint2 raw = *(const uint2*)(X16 + (size_t)src * HH + lane * 4);
        __half2 p0 = *(__half2*)&raw.x;
        __half2 p1 = *(__half2*)&raw.y;
        float2 f0 = __half22float2(p0);
        float2 f1 = __half22float2(p1);
        #pragma unroll
        for (int b = 0; b < NB; b++) {
            float w = s_comp[t * NB + b] * ic;
            acc[b].x += w * f0.x; acc[b].y += w * f0.y;
            acc[b].z += w * f1.x; acc[b].w += w * f1.y;
        }
    }

    size_t base = (size_t)warp * 512 + lane * 4;
    #pragma unroll
    for (int b = 0; b < NB; b++) {
        uint32_t h0, h1, l0, l1;
        split2(acc[b].x, acc[b].y, h0, l0);
        split2(acc[b].z, acc[b].w, h1, l1);
        *(uint2*)(d_z_hi + base + b * 128) = make_uint2(h0, h1);
        *(uint2*)(d_z_lo + base + b * 128) = make_uint2(l0, l1);
    }
}

// ---------------- tensor-core GEMM: cp.async double-buffered HMMA --------------
__global__ void __launch_bounds__(256, 1)
tc_gemm_kernel(const __nv_bfloat16* __restrict__ Xhi, const __nv_bfloat16* __restrict__ Xlo,
               float* __restrict__ OUT,                 // fp32 (layer 3 only)
               __half* __restrict__ OUT16,              // fp16 (layers 1,2)
               __nv_bfloat16* __restrict__ OUThi, __nv_bfloat16* __restrict__ OUTlo,
               const float* __restrict__ bias, int relu, int layer) {
    extern __shared__ __align__(1024) char smem[];
    uint32_t sb = smem_u32(smem);
    int tid = threadIdx.x;
    int wid = tid >> 5;
    int lane = tid & 31;
    int row0 = blockIdx.x * MTILE;

    const __nv_bfloat16* Whi = d_wt_hi + (size_t)layer * NTILE * KTOT;
    const __nv_bfloat16* Wlo = d_wt_lo + (size_t)layer * NTILE * KTOT;

    int lr[4], lc[4];
    uint32_t ldst[4];
    #pragma unroll
    for (int i = 0; i < 4; i++) {
        int g = tid + i * 256;
        lr[i] = g >> 3;
        lc[i] = (g & 7) * 8;
        ldst[i] = SW128((uint32_t)(lr[i] * 128 + lc[i] * 2));
    }

    #define LOAD_CHUNK(c, stage)                                                      \
    {                                                                                 \
        uint32_t s0 = sb + (stage) * STAGE_BYTES;                                     \
        _Pragma("unroll")                                                             \
        for (int i = 0; i < 4; i++) {                                                 \
            int gm = row0 + lr[i];                                                    \
            const __nv_bfloat16 *ah, *al;                                             \
            if ((c) < 8) {                                                            \
                ah = d_z_hi + (size_t)gm * 512 + (c) * KCHUNK + lc[i];                \
                al = d_z_lo + (size_t)gm * 512 + (c) * KCHUNK + lc[i];                \
            } else {                                                                  \
                ah = Xhi + (size_t)gm * 128 + ((c) - 8) * KCHUNK + lc[i];             \
                al = Xlo + (size_t)gm * 128 + ((c) - 8) * KCHUNK + lc[i];             \
            }                                                                         \
            cp16(s0 + ldst[i], ah);                                                   \
            cp16(s0 + 16384 + ldst[i], al);                                           \
            const __nv_bfloat16* bh = Whi + (size_t)lr[i] * KTOT + (c) * KCHUNK + lc[i]; \
            const __nv_bfloat16* bl = Wlo + (size_t)lr[i] * KTOT + (c) * KCHUNK + lc[i]; \
            cp16(s0 + 32768 + ldst[i], bh);                                           \
            cp16(s0 + 49152 + ldst[i], bl);                                           \
        }                                                                             \
    }

    int wm = (wid & 1) * 64;
    int wn = (wid >> 1) * 32;

    int sub = lane & 7, g = lane >> 3;
    int a_r = sub + ((g & 1) << 3);
    int a_k = (g >> 1) << 3;
    int b_r = sub + ((g >> 1) << 3);
    int b_k = (g & 1) << 3;

    float acc[4][4][4];
    #pragma unroll
    for (int mt = 0; mt < 4; mt++)
        #pragma unroll
        for (int nt = 0; nt < 4; nt++)
            #pragma unroll
            for (int q = 0; q < 4; q++) acc[mt][nt][q] = 0.0f;

    LOAD_CHUNK(0, 0);
    cp_commit();

    for (int c = 0; c < NCHUNKS; c++) {
        if (c + 1 < NCHUNKS) {
            LOAD_CHUNK(c + 1, (c + 1) & 1);
            cp_commit();
            cp_wait<1>();
        } else {
            cp_wait<0>();
        }
        __syncthreads();

        uint32_t s0 = sb + (c & 1) * STAGE_BYTES;
        #pragma unroll
        for (int ks = 0; ks < 4; ks++) {
            uint32_t ah[4][4], al[4][4], bh[2][4], bl[2][4];
            #pragma unroll
            for (int mt = 0; mt < 4; mt++) {
                uint32_t off = SW128((uint32_t)((wm + mt * 16 + a_r) * 128 + (ks * 16 + a_k) * 2));
                ldsm_x4(ah[mt], s0 + off);
                ldsm_x4(al[mt], s0 + 16384 + off);
            }
            #pragma unroll
            for (int nt2 = 0; nt2 < 2; nt2++) {
                uint32_t off = SW128((uint32_t)((wn + nt2 * 16 + b_r) * 128 + (ks * 16 + b_k) * 2));
                ldsm_x4(bh[nt2], s0 + 32768 + off);
                ldsm_x4(bl[nt2], s0 + 49152 + off);
            }
            #pragma unroll
            for (int mt = 0; mt < 4; mt++)
                #pragma unroll
                for (int nt = 0; nt < 4; nt++) {
                    uint32_t b0h = bh[nt >> 1][(nt & 1) * 2], b1h = bh[nt >> 1][(nt & 1) * 2 + 1];
                    uint32_t b0l = bl[nt >> 1][(nt & 1) * 2], b1l = bl[nt >> 1][(nt & 1) * 2 + 1];
                    mma_bf16(acc[mt][nt], ah[mt], b0h, b1h);
                    mma_bf16(acc[mt][nt], ah[mt], b0l, b1l);
                    mma_bf16(acc[mt][nt], al[mt], b0h, b1h);
                }
        }
        __syncthreads();
    }
    #undef LOAD_CHUNK

    // ---- epilogue
    #pragma unroll
    for (int mt = 0; mt < 4; mt++) {
        int rr2[2];
        rr2[0] = row0 + wm + mt * 16 + (lane >> 2);
        rr2[1] = rr2[0] + 8;
        #pragma unroll
        for (int nt = 0; nt < 4; nt++) {
            int col = wn + nt * 8 + ((lane & 3) << 1);
            float2 b2 = *(const float2*)(bias + col);
            #pragma unroll
            for (int half2i = 0; half2i < 2; half2i++) {
                int r = rr2[half2i];
                if (r >= NN) continue;
                float2 v;
                v.x = acc[mt][nt][half2i * 2 + 0] + b2.x;
                v.y = acc[mt][nt][half2i * 2 + 1] + b2.y;
                if (relu) { v.x = fmaxf(v.x, 0.f); v.y = fmaxf(v.y, 0.f); }
                if (OUT) *(float2*)(OUT + (size_t)r * 128 + col) = v;
                if (OUT16) *(__half2*)(OUT16 + (size_t)r * 128 + col) = __float22half2_rn(v);
                if (OUThi) {
                    uint32_t h, l;
                    split2(v.x, v.y, h, l);
                    *(uint32_t*)(OUThi + (size_t)r * 128 + col) = h;
                    *(uint32_t*)(OUTlo + (size_t)r * 128 + col) = l;
                }
            }
        }
    }
}

// ---------------- pooling ----------------
__global__ void pool_kernel(const int* __restrict__ batch) {
    int warp = (blockIdx.x * blockDim.x + threadIdx.x) >> 5;
    int lane = threadIdx.x & 31;
    if (warp >= NN) return;
    int g = __ldg(batch + warp);
    float4 v = *(const float4*)(d_h1 + (size_t)warp * 128 + lane * 4);
    atomicAdd(&d_pool[g * 128 + lane * 4 + 0], v.x);
    atomicAdd(&d_pool[g * 128 + lane * 4 + 1], v.y);
    atomicAdd(&d_pool[g * 128 + lane * 4 + 2], v.z);
    atomicAdd(&d_pool[g * 128 + lane * 4 + 3], v.w);
    if (lane == 0) atomicAdd(&d_poolcnt[g], 1.0f);
}

__global__ void final_kernel(const int* __restrict__ rl,
                             const float* __restrict__ rel_emb,
                             const float* __restrict__ lw,   // [256,2]
                             const float* __restrict__ lb,   // [2]
                             float* __restrict__ out) {
    int t = threadIdx.x;
    if (t >= GG * NC) return;
    int g = t >> 1, c = t & 1;
    float cnt = d_poolcnt[g];
    float invc = 1.0f / (cnt > 1.0f ? cnt : 1.0f);
    const float* re = rel_emb + (size_t)rl[g] * 128;
    float s = 0.f;
    for (int j = 0; j < 128; j++) s += d_pool[g * 128 + j] * invc * lw[j * 2 + c];
    for (int j = 0; j < 128; j++) s += re[j] * lw[(128 + j) * 2 + c];
    out[g * 2 + c] = s + lb[c];
}

// ---------------- launch ----------------
extern "C" void kernel_launch(void* const* d_in, const int* in_sizes, int n_in,
                              void* d_out, int out_size) {
    const float* x      = (const float*)d_in[0];
    const int*   ei     = (const int*)d_in[1];
    const int*   et     = (const int*)d_in[2];
    const int*   batch  = (const int*)d_in[3];
    const int*   rl     = (const int*)d_in[4];
    const float* relemb = (const float*)d_in[6];
    const float* bases[3] = {(const float*)d_in[7],  (const float*)d_in[11], (const float*)d_in[15]};
    const float* comp[3]  = {(const float*)d_in[8],  (const float*)d_in[12], (const float*)d_in[16]};
    const float* root[3]  = {(const float*)d_in[9],  (const float*)d_in[13], (const float*)d_in[17]};
    const float* bias[3]  = {(const float*)d_in[10], (const float*)d_in[14], (const float*)d_in[18]};
    const float* lin_w  = (const float*)d_in[19];
    const float* lin_b  = (const float*)d_in[20];
    float* out = (float*)d_out;

    cudaFuncSetAttribute(tc_gemm_kernel, cudaFuncAttributeMaxDynamicSharedMemorySize, GEMM_SMEM);

    void *p_h1, *p_x16, *p_h116, *p_h216;
    void *p_xh, *p_xl, *p_h1h, *p_h1l, *p_h2h, *p_h2l;
    cudaGetSymbolAddress(&p_h1, d_h1);
    cudaGetSymbolAddress(&p_x16, d_x16);
    cudaGetSymbolAddress(&p_h116, d_h1_16);
    cudaGetSymbolAddress(&p_h216, d_h2_16);
    cudaGetSymbolAddress(&p_xh, d_x_hi);
    cudaGetSymbolAddress(&p_xl, d_x_lo);
    cudaGetSymbolAddress(&p_h1h, d_h1_hi);
    cudaGetSymbolAddress(&p_h1l, d_h1_lo);
    cudaGetSymbolAddress(&p_h2h, d_h2_hi);
    cudaGetSymbolAddress(&p_h2l, d_h2_lo);

    const int TB = 256;
    zero_init_kernel<<<(NN * RR + TB - 1) / TB, TB>>>();
    count_kernel<<<(EE + TB - 1) / TB, TB>>>(ei, et);
    scan_kernel<<<1, 1024>>>();
    invcnt_kernel<<<(NN * RR + TB - 1) / TB, TB>>>();
    scatter_kernel<<<(EE + TB - 1) / TB, TB>>>(ei, et);
    xsplit_kernel<<<(NN * HH / 2 + TB - 1) / TB, TB>>>(x);

    int wpBlocks = (KTOT * NTILE + TB - 1) / TB;
    wprep_kernel<<<wpBlocks, TB>>>(bases[0], root[0], 0);
    wprep_kernel<<<wpBlocks, TB>>>(bases[1], root[1], 1);
    wprep_kernel<<<wpBlocks, TB>>>(bases[2], root[2], 2);

    int aggBlocks = (NN * 32 + TB - 1) / TB;

    // layer 1: agg(x16) -> z; gemm -> h1 (fp16 + bf16 hi/lo), relu
    agg_kernel<<<aggBlocks, TB>>>((const __half*)p_x16, comp[0]);
    tc_gemm_kernel<<<GEMM_GRID, 256, GEMM_SMEM>>>(
        (const __nv_bfloat16*)p_xh, (const __nv_bfloat16*)p_xl,
        (float*)nullptr, (__half*)p_h116,
        (__nv_bfloat16*)p_h1h, (__nv_bfloat16*)p_h1l, bias[0], 1, 0);
    // layer 2: agg(h1_16) -> z; gemm -> h2 (fp16 + bf16 hi/lo), relu
    agg_kernel<<<aggBlocks, TB>>>((const __half*)p_h116, comp[1]);
    tc_gemm_kernel<<<GEMM_GRID, 256, GEMM_SMEM>>>(
        (const __nv_bfloat16*)p_h1h, (const __nv_bfloat16*)p_h1l,
        (float*)nullptr, (__half*)p_h216,
        (__nv_bfloat16*)p_h2h, (__nv_bfloat16*)p_h2l, bias[1], 1, 1);
    // layer 3: agg(h2_16) -> z; gemm -> h1 fp32 only, no relu
    agg_kernel<<<aggBlocks, TB>>>((const __half*)p_h216, comp[2]);
    tc_gemm_kernel<<<GEMM_GRID, 256, GEMM_SMEM>>>(
        (const __nv_bfloat16*)p_h2h, (const __nv_bfloat16*)p_h2l,
        (float*)p_h1, (__half*)nullptr,
        (__nv_bfloat16*)nullptr, (__nv_bfloat16*)nullptr, bias[2], 0, 2);

    pool_kernel<<<aggBlocks, TB>>>(batch);
    final_kernel<<<1, 128>>>(rl, relemb, lin_w, lin_b, out);
}

// round 9
// speedup vs baseline: 2.0010x; 1.1901x over previous
#include <cuda_runtime.h>
#include <cuda_bf16.h>
#include <cuda_fp16.h>
#include <cstdint>

// Problem constants
#define NN   50000
#define NPAD 50048
#define EE   1600000
#define RR   16
#define NB   4
#define HH   128
#define GG   64
#define NC   2

#define KTOT 640
#define MTILE 128
#define NTILE 128
#define KCHUNK 64
#define NCHUNKS 10
#define GEMM_GRID ((NN + MTILE - 1) / MTILE)   // 391
#define STAGE_BYTES 65536
#define GEMM_SMEM (2 * STAGE_BYTES)

// ---------------- device scratch (static, no allocs) ----------------
__device__ unsigned int d_csr[EE];
__device__ int   d_rowptr[NN + 1];
__device__ int   d_deg[NN];
__device__ int   d_cursor[NN];
__device__ int   d_cnt[NN * RR];
__device__ float d_invcnt[NN * RR];
__device__ float d_pool[GG * HH];
__device__ float d_poolcnt[GG];
// fp16 gather mirrors
__device__ __half d_x16[(size_t)NPAD * HH];
__device__ __half d_h1_16[(size_t)NPAD * HH];
__device__ __half d_h2_16[(size_t)NPAD * HH];
// pre-split bf16 operands (padded rows)
__device__ __nv_bfloat16 d_z_hi[(size_t)NPAD * 512];
__device__ __nv_bfloat16 d_z_lo[(size_t)NPAD * 512];
__device__ __nv_bfloat16 d_x_hi[(size_t)NPAD * HH];
__device__ __nv_bfloat16 d_x_lo[(size_t)NPAD * HH];
__device__ __nv_bfloat16 d_h1_hi[(size_t)NPAD * HH];
__device__ __nv_bfloat16 d_h1_lo[(size_t)NPAD * HH];
__device__ __nv_bfloat16 d_h2_hi[(size_t)NPAD * HH];
__device__ __nv_bfloat16 d_h2_lo[(size_t)NPAD * HH];
// transposed + hi/lo split weights: [layer][n(128)][k(640)]
__device__ __nv_bfloat16 d_wt_hi[3 * NTILE * KTOT];
__device__ __nv_bfloat16 d_wt_lo[3 * NTILE * KTOT];

// ---------------- helpers ----------------
__device__ __forceinline__ uint32_t smem_u32(const void* p) {
    uint32_t a;
    asm("{ .reg .u64 t; cvta.to.shared.u64 t, %1; cvt.u32.u64 %0, t; }" : "=r"(a) : "l"(p));
    return a;
}
#define SW128(o) ((o) ^ (((o) >> 3) & 0x70))

__device__ __forceinline__ void split2(float a, float b, uint32_t& hi, uint32_t& lo) {
    __nv_bfloat16 ha = __float2bfloat16(a), hb = __float2bfloat16(b);
    float fa = __bfloat162float(ha), fb = __bfloat162float(hb);
    __nv_bfloat16 la = __float2bfloat16(a - fa), lb = __float2bfloat16(b - fb);
    hi = (uint32_t)__bfloat16_as_ushort(ha) | ((uint32_t)__bfloat16_as_ushort(hb) << 16);
    lo = (uint32_t)__bfloat16_as_ushort(la) | ((uint32_t)__bfloat16_as_ushort(lb) << 16);
}

__device__ __forceinline__ void ldsm_x4(uint32_t* r, uint32_t addr) {
    asm volatile("ldmatrix.sync.aligned.m8n8.x4.shared.b16 {%0,%1,%2,%3}, [%4];"
                 : "=r"(r[0]), "=r"(r[1]), "=r"(r[2]), "=r"(r[3]) : "r"(addr));
}
__device__ __forceinline__ void mma_bf16(float* d, const uint32_t* a, uint32_t b0, uint32_t b1) {
    asm volatile(
        "mma.sync.aligned.m16n8k16.row.col.f32.bf16.bf16.f32 "
        "{%0,%1,%2,%3}, {%4,%5,%6,%7}, {%8,%9}, {%0,%1,%2,%3};"
        : "+f"(d[0]), "+f"(d[1]), "+f"(d[2]), "+f"(d[3])
        : "r"(a[0]), "r"(a[1]), "r"(a[2]), "r"(a[3]), "r"(b0), "r"(b1));
}
__device__ __forceinline__ void cp16(uint32_t smem_dst, const void* gsrc) {
    asm volatile("cp.async.cg.shared.global [%0], [%1], 16;" :: "r"(smem_dst), "l"(gsrc));
}
__device__ __forceinline__ void cp_commit() {
    asm volatile("cp.async.commit_group;" ::: "memory");
}
template<int N> __device__ __forceinline__ void cp_wait() {
    asm volatile("cp.async.wait_group %0;" :: "n"(N) : "memory");
}

// ---------------- init ----------------
__global__ void zero_init_kernel() {
    int i = blockIdx.x * blockDim.x + threadIdx.x;
    if (i < NN * RR) d_cnt[i] = 0;
    if (i < NN) d_cursor[i] = 0;
    if (i < GG * HH) d_pool[i] = 0.0f;
    if (i < GG) d_poolcnt[i] = 0.0f;
}

// ---------------- one-time x split: fp32 -> bf16 hi/lo + fp16 ----------------
__global__ void xsplit_kernel(const float* __restrict__ x) {
    int i = blockIdx.x * blockDim.x + threadIdx.x;
    if (i >= NN * HH / 2) return;
    float2 v = *(const float2*)(x + i * 2);
    uint32_t h, l;
    split2(v.x, v.y, h, l);
    *(uint32_t*)((__nv_bfloat16*)d_x_hi + (size_t)i * 2) = h;
    *(uint32_t*)((__nv_bfloat16*)d_x_lo + (size_t)i * 2) = l;
    __half2 p = __float22half2_rn(v);
    *(__half2*)(d_x16 + (size_t)i * 2) = p;
}

// ---------------- weight prep: transpose + hi/lo split ----------------
__global__ void wprep_kernel(const float* __restrict__ bases,
                             const float* __restrict__ root, int layer) {
    int i = blockIdx.x * blockDim.x + threadIdx.x;
    if (i >= KTOT * NTILE) return;
    int k = i >> 7, n = i & 127;
    float w = (k < 512) ? bases[k * 128 + n] : root[(k - 512) * 128 + n];
    __nv_bfloat16 h = __float2bfloat16(w);
    float hf = __bfloat162float(h);
    __nv_bfloat16 l = __float2bfloat16(w - hf);
    size_t o = (size_t)layer * NTILE * KTOT + (size_t)n * KTOT + k;
    d_wt_hi[o] = h;
    d_wt_lo[o] = l;
}

// ---------------- CSR build ----------------
__global__ void count_kernel(const int* __restrict__ ei, const int* __restrict__ et) {
    int e = blockIdx.x * blockDim.x + threadIdx.x;
    if (e >= EE) return;
    int dst = __ldg(ei + EE + e);
    int t   = __ldg(et + e);
    atomicAdd(&d_cnt[dst * RR + t], 1);
}

// per-node: deg from cnt, invcnt, poolcnt
__global__ void deg_kernel(const int* __restrict__ batch) {
    int n = blockIdx.x * blockDim.x + threadIdx.x;
    if (n >= NN) return;
    const int4* c4 = (const int4*)(d_cnt + n * RR);
    int deg = 0;
    float4* iv = (float4*)(d_invcnt + n * RR);
    #pragma unroll
    for (int q = 0; q < 4; q++) {
        int4 c = c4[q];
        deg += c.x + c.y + c.z + c.w;
        float4 f;
        f.x = 1.0f / (float)(c.x > 1 ? c.x : 1);
        f.y = 1.0f / (float)(c.y > 1 ? c.y : 1);
        f.z = 1.0f / (float)(c.z > 1 ? c.z : 1);
        f.w = 1.0f / (float)(c.w > 1 ? c.w : 1);
        iv[q] = f;
    }
    d_deg[n] = deg;
    atomicAdd(&d_poolcnt[__ldg(batch + n)], 1.0f);
}

__global__ void scan_kernel() {   // 1 block, 1024 threads
    const int T = 1024;
    __shared__ int sh[T];
    int tid = threadIdx.x;
    int chunk = (NN + T - 1) / T;
    int start = tid * chunk;
    int endi  = start + chunk; if (endi > NN) endi = NN;
    int s = 0;
    for (int i = start; i < endi && start < NN; i++) s += d_deg[i];
    sh[tid] = (start < NN) ? s : 0;
    __syncthreads();
    for (int off = 1; off < T; off <<= 1) {
        int v = (tid >= off) ? sh[tid - off] : 0;
        __syncthreads();
        if (tid >= off) sh[tid] += v;
        __syncthreads();
    }
    int run = (tid == 0) ? 0 : sh[tid - 1];
    if (start < NN) {
        for (int i = start; i < endi; i++) { d_rowptr[i] = run; run += d_deg[i]; }
    }
    if (tid == T - 1) d_rowptr[NN] = sh[T - 1];
}

__global__ void scatter_kernel(const int* __restrict__ ei, const int* __restrict__ et) {
    int e = blockIdx.x * blockDim.x + threadIdx.x;
    if (e >= EE) return;
    int src = __ldg(ei + e);
    int dst = __ldg(ei + EE + e);
    int t   = __ldg(et + e);
    int pos = d_rowptr[dst] + atomicAdd(&d_cursor[dst], 1);
    d_csr[pos] = (unsigned)src | ((unsigned)t << 20);
}

// ---------------- per-layer aggregation (fp16 gather) -> z_hi/z_lo bf16 -------
// one warp per node. CSR entries loaded coalesced (32 at a time), broadcast by
// shuffle -> gather addresses never depend on an in-flight load (MLP ~8).
__global__ void agg_kernel(const __half* __restrict__ X16,
                           const float* __restrict__ comp /*[R,NB]*/) {
    __shared__ float4 s_comp4[RR];
    int tid = threadIdx.x;
    if (tid < RR) s_comp4[tid] = *(const float4*)(comp + tid * NB);
    __syncthreads();

    int warp = (blockIdx.x * blockDim.x + tid) >> 5;
    int lane = tid & 31;
    if (warp >= NN) return;

    int beg = d_rowptr[warp];
    int end = d_rowptr[warp + 1];
    float inv_t = (lane < RR) ? d_invcnt[warp * RR + lane] : 0.0f;

    float4 acc[NB];
    #pragma unroll
    for (int b = 0; b < NB; b++) acc[b] = make_float4(0.f, 0.f, 0.f, 0.f);

    const __half* Xl = X16 + lane * 4;

    int i = beg;
    // full blocks of 32 edges: one coalesced csr load per block
    for (; i + 32 <= end; i += 32) {
        unsigned pv = d_csr[i + lane];
        #pragma unroll 8
        for (int j = 0; j < 32; j++) {
            unsigned p = __shfl_sync(0xffffffffu, pv, j);
            int src = (int)(p & 0xFFFFFu);
            int t   = (int)(p >> 20);
            float ic = __shfl_sync(0xffffffffu, inv_t, t);
            uint2 raw = *(const uint2*)(Xl + (size_t)src * HH);
            float2 f0 = __half22float2(*(__half2*)&raw.x);
            float2 f1 = __half22float2(*(__half2*)&raw.y);
            float4 cw = s_comp4[t];
            acc[0].x += cw.x * ic * f0.x; acc[0].y += cw.x * ic * f0.y;
            acc[0].z += cw.x * ic * f1.x; acc[0].w += cw.x * ic * f1.y;
            acc[1].x += cw.y * ic * f0.x; acc[1].y += cw.y * ic * f0.y;
            acc[1].z += cw.y * ic * f1.x; acc[1].w += cw.y * ic * f1.y;
            acc[2].x += cw.z * ic * f0.x; acc[2].y += cw.z * ic * f0.y;
            acc[2].z += cw.z * ic * f1.x; acc[2].w += cw.z * ic * f1.y;
            acc[3].x += cw.w * ic * f0.x; acc[3].y += cw.w * ic * f0.y;
            acc[3].z += cw.w * ic * f1.x; acc[3].w += cw.w * ic * f1.y;
        }
    }
    // tail (broadcast load, < 32 edges)
    for (; i < end; i++) {
        unsigned p = d_csr[i];
        int src = (int)(p & 0xFFFFFu);
        int t   = (int)(p >> 20);
        float ic = __shfl_sync(0xffffffffu, inv_t, t);
        uint2 raw = *(const uint2*)(Xl + (size_t)src * HH);
        float2 f0 = __half22float2(*(__half2*)&raw.x);
        float2 f1 = __half22float2(*(__half2*)&raw.y);
        float4 cw = s_comp4[t];
        acc[0].x += cw.x * ic * f0.x; acc[0].y += cw.x * ic * f0.y;
        acc[0].z += cw.x * ic * f1.x; acc[0].w += cw.x * ic * f1.y;
        acc[1].x += cw.y * ic * f0.x; acc[1].y += cw.y * ic * f0.y;
        acc[1].z += cw.y * ic * f1.x; acc[1].w += cw.y * ic * f1.y;
        acc[2].x += cw.z * ic * f0.x; acc[2].y += cw.z * ic * f0.y;
        acc[2].z += cw.z * ic * f1.x; acc[2].w += cw.z * ic * f1.y;
        acc[3].x += cw.w * ic * f0.x; acc[3].y += cw.w * ic * f0.y;
        acc[3].z += cw.w * ic * f1.x; acc[3].w += cw.w * ic * f1.y;
    }

    size_t base = (size_t)warp * 512 + lane * 4;
    #pragma unroll
    for (int b = 0; b < NB; b++) {
        uint32_t h0, h1, l0, l1;
        split2(acc[b].x, acc[b].y, h0, l0);
        split2(acc[b].z, acc[b].w, h1, l1);
        *(uint2*)(d_z_hi + base + b * 128) = make_uint2(h0, h1);
        *(uint2*)(d_z_lo + base + b * 128) = make_uint2(l0, l1);
    }
}

// ---------------- tensor-core GEMM: cp.async double-buffered HMMA --------------
__global__ void __launch_bounds__(256, 1)
tc_gemm_kernel(const __nv_bfloat16* __restrict__ Xhi, const __nv_bfloat16* __restrict__ Xlo,
               __half* __restrict__ OUT16,              // fp16 (layers 1,2)
               __nv_bfloat16* __restrict__ OUThi, __nv_bfloat16* __restrict__ OUTlo,
               const float* __restrict__ bias, int relu, int layer,
               int do_pool, const int* __restrict__ batch) {
    extern __shared__ __align__(1024) char smem[];
    uint32_t sb = smem_u32(smem);
    int tid = threadIdx.x;
    int wid = tid >> 5;
    int lane = tid & 31;
    int row0 = blockIdx.x * MTILE;

    const __nv_bfloat16* Whi = d_wt_hi + (size_t)layer * NTILE * KTOT;
    const __nv_bfloat16* Wlo = d_wt_lo + (size_t)layer * NTILE * KTOT;

    int lr[4], lc[4];
    uint32_t ldst[4];
    #pragma unroll
    for (int i = 0; i < 4; i++) {
        int g = tid + i * 256;
        lr[i] = g >> 3;
        lc[i] = (g & 7) * 8;
        ldst[i] = SW128((uint32_t)(lr[i] * 128 + lc[i] * 2));
    }

    #define LOAD_CHUNK(c, stage)                                                      \
    {                                                                                 \
        uint32_t s0 = sb + (stage) * STAGE_BYTES;                                     \
        _Pragma("unroll")                                                             \
        for (int i = 0; i < 4; i++) {                                                 \
            int gm = row0 + lr[i];                                                    \
            const __nv_bfloat16 *ah, *al;                                             \
            if ((c) < 8) {                                                            \
                ah = d_z_hi + (size_t)gm * 512 + (c) * KCHUNK + lc[i];                \
                al = d_z_lo + (size_t)gm * 512 + (c) * KCHUNK + lc[i];                \
            } else {                                                                  \
                ah = Xhi + (size_t)gm * 128 + ((c) - 8) * KCHUNK + lc[i];             \
                al = Xlo + (size_t)gm * 128 + ((c) - 8) * KCHUNK + lc[i];             \
            }                                                                         \
            cp16(s0 + ldst[i], ah);                                                   \
            cp16(s0 + 16384 + ldst[i], al);                                           \
            const __nv_bfloat16* bh = Whi + (size_t)lr[i] * KTOT + (c) * KCHUNK + lc[i]; \
            const __nv_bfloat16* bl = Wlo + (size_t)lr[i] * KTOT + (c) * KCHUNK + lc[i]; \
            cp16(s0 + 32768 + ldst[i], bh);                                           \
            cp16(s0 + 49152 + ldst[i], bl);                                           \
        }                                                                             \
    }

    int wm = (wid & 1) * 64;
    int wn = (wid >> 1) * 32;

    int sub = lane & 7, g = lane >> 3;
    int a_r = sub + ((g & 1) << 3);
    int a_k = (g >> 1) << 3;
    int b_r = sub + ((g >> 1) << 3);
    int b_k = (g & 1) << 3;

    float acc[4][4][4];
    #pragma unroll
    for (int mt = 0; mt < 4; mt++)
        #pragma unroll
        for (int nt = 0; nt < 4; nt++)
            #pragma unroll
            for (int q = 0; q < 4; q++) acc[mt][nt][q] = 0.0f;

    LOAD_CHUNK(0, 0);
    cp_commit();

    for (int c = 0; c < NCHUNKS; c++) {
        if (c + 1 < NCHUNKS) {
            LOAD_CHUNK(c + 1, (c + 1) & 1);
            cp_commit();
            cp_wait<1>();
        } else {
            cp_wait<0>();
        }
        __syncthreads();

        uint32_t s0 = sb + (c & 1) * STAGE_BYTES;
        #pragma unroll
        for (int ks = 0; ks < 4; ks++) {
            uint32_t ah[4][4], al[4][4], bh[2][4], bl[2][4];
            #pragma unroll
            for (int mt = 0; mt < 4; mt++) {
                uint32_t off = SW128((uint32_t)((wm + mt * 16 + a_r) * 128 + (ks * 16 + a_k) * 2));
                ldsm_x4(ah[mt], s0 + off);
                ldsm_x4(al[mt], s0 + 16384 + off);
            }
            #pragma unroll
            for (int nt2 = 0; nt2 < 2; nt2++) {
                uint32_t off = SW128((uint32_t)((wn + nt2 * 16 + b_r) * 128 + (ks * 16 + b_k) * 2));
                ldsm_x4(bh[nt2], s0 + 32768 + off);
                ldsm_x4(bl[nt2], s0 + 49152 + off);
            }
            #pragma unroll
            for (int mt = 0; mt < 4; mt++)
                #pragma unroll
                for (int nt = 0; nt < 4; nt++) {
                    uint32_t b0h = bh[nt >> 1][(nt & 1) * 2], b1h = bh[nt >> 1][(nt & 1) * 2 + 1];
                    uint32_t b0l = bl[nt >> 1][(nt & 1) * 2], b1l = bl[nt >> 1][(nt & 1) * 2 + 1];
                    mma_bf16(acc[mt][nt], ah[mt], b0h, b1h);
                    mma_bf16(acc[mt][nt], ah[mt], b0l, b1l);
                    mma_bf16(acc[mt][nt], al[mt], b0h, b1h);
                }
        }
        __syncthreads();
    }
    #undef LOAD_CHUNK

    if (!do_pool) {
        // ---- store epilogue (layers 1,2)
        #pragma unroll
        for (int mt = 0; mt < 4; mt++) {
            int rr2[2];
            rr2[0] = row0 + wm + mt * 16 + (lane >> 2);
            rr2[1] = rr2[0] + 8;
            #pragma unroll
            for (int nt = 0; nt < 4; nt++) {
                int col = wn + nt * 8 + ((lane & 3) << 1);
                float2 b2 = *(const float2*)(bias + col);
                #pragma unroll
                for (int h2i = 0; h2i < 2; h2i++) {
                    int r = rr2[h2i];
                    if (r >= NN) continue;
                    float2 v;
                    v.x = acc[mt][nt][h2i * 2 + 0] + b2.x;
                    v.y = acc[mt][nt][h2i * 2 + 1] + b2.y;
                    if (relu) { v.x = fmaxf(v.x, 0.f); v.y = fmaxf(v.y, 0.f); }
                    *(__half2*)(OUT16 + (size_t)r * 128 + col) = __float22half2_rn(v);
                    uint32_t h, l;
                    split2(v.x, v.y, h, l);
                    *(uint32_t*)(OUThi + (size_t)r * 128 + col) = h;
                    *(uint32_t*)(OUTlo + (size_t)r * 128 + col) = l;
                }
            }
        }
    } else {
        // ---- pooling epilogue (layer 3): accumulate rows of the same graph,
        // flush one atomic per (graph, col) run. Rows visited in increasing order.
        float pacc[8];
        int curg = -1;
        int colb = wn + ((lane & 3) << 1);
        #pragma unroll
        for (int mt = 0; mt < 4; mt++) {
            #pragma unroll
            for (int h2i = 0; h2i < 2; h2i++) {
                int r = row0 + wm + mt * 16 + (lane >> 2) + h2i * 8;
                if (r >= NN) continue;
                int gph = __ldg(batch + r);
                if (gph != curg) {
                    if (curg >= 0) {
                        #pragma unroll
                        for (int j = 0; j < 4; j++) {
                            atomicAdd(&d_pool[curg * 128 + colb + j * 8], pacc[j * 2]);
                            atomicAdd(&d_pool[curg * 128 + colb + j * 8 + 1], pacc[j * 2 + 1]);
                        }
                    }
                    curg = gph;
                    #pragma unroll
                    for (int j = 0; j < 8; j++) pacc[j] = 0.f;
                }
                #pragma unroll
                for (int nt = 0; nt < 4; nt++) {
                    float2 b2 = *(const float2*)(bias + colb + nt * 8);
                    pacc[nt * 2 + 0] += acc[mt][nt][h2i * 2 + 0] + b2.x;
                    pacc[nt * 2 + 1] += acc[mt][nt][h2i * 2 + 1] + b2.y;
                }
            }
        }
        if (curg >= 0) {
            #pragma unroll
            for (int j = 0; j < 4; j++) {
                atomicAdd(&d_pool[curg * 128 + colb + j * 8], pacc[j * 2]);
                atomicAdd(&d_pool[curg * 128 + colb + j * 8 + 1], pacc[j * 2 + 1]);
            }
        }
    }
}

// ---------------- final ----------------
__global__ void final_kernel(const int* __restrict__ rl,
                             const float* __restrict__ rel_emb,
                             const float* __restrict__ lw,   // [256,2]
                             const float* __restrict__ lb,   // [2]
                             float* __restrict__ out) {
    int t = threadIdx.x;
    if (t >= GG * NC) return;
    int g = t >> 1, c = t & 1;
    float cnt = d_poolcnt[g];
    float invc = 1.0f / (cnt > 1.0f ? cnt : 1.0f);
    const float* re = rel_emb + (size_t)rl[g] * 128;
    float s = 0.f;
    for (int j = 0; j < 128; j++) s += d_pool[g * 128 + j] * invc * lw[j * 2 + c];
    for (int j = 0; j < 128; j++) s += re[j] * lw[(128 + j) * 2 + c];
    out[g * 2 + c] = s + lb[c];
}

// ---------------- launch ----------------
extern "C" void kernel_launch(void* const* d_in, const int* in_sizes, int n_in,
                              void* d_out, int out_size) {
    const float* x      = (const float*)d_in[0];
    const int*   ei     = (const int*)d_in[1];
    const int*   et     = (const int*)d_in[2];
    const int*   batch  = (const int*)d_in[3];
    const int*   rl     = (const int*)d_in[4];
    const float* relemb = (const float*)d_in[6];
    const float* bases[3] = {(const float*)d_in[7],  (const float*)d_in[11], (const float*)d_in[15]};
    const float* comp[3]  = {(const float*)d_in[8],  (const float*)d_in[12], (const float*)d_in[16]};
    const float* root[3]  = {(const float*)d_in[9],  (const float*)d_in[13], (const float*)d_in[17]};
    const float* bias[3]  = {(const float*)d_in[10], (const float*)d_in[14], (const float*)d_in[18]};
    const float* lin_w  = (const float*)d_in[19];
    const float* lin_b  = (const float*)d_in[20];
    float* out = (float*)d_out;

    cudaFuncSetAttribute(tc_gemm_kernel, cudaFuncAttributeMaxDynamicSharedMemorySize, GEMM_SMEM);

    void *p_x16, *p_h116, *p_h216;
    void *p_xh, *p_xl, *p_h1h, *p_h1l, *p_h2h, *p_h2l;
    cudaGetSymbolAddress(&p_x16, d_x16);
    cudaGetSymbolAddress(&p_h116, d_h1_16);
    cudaGetSymbolAddress(&p_h216, d_h2_16);
    cudaGetSymbolAddress(&p_xh, d_x_hi);
    cudaGetSymbolAddress(&p_xl, d_x_lo);
    cudaGetSymbolAddress(&p_h1h, d_h1_hi);
    cudaGetSymbolAddress(&p_h1l, d_h1_lo);
    cudaGetSymbolAddress(&p_h2h, d_h2_hi);
    cudaGetSymbolAddress(&p_h2l, d_h2_lo);

    const int TB = 256;
    zero_init_kernel<<<(NN * RR + TB - 1) / TB, TB>>>();
    count_kernel<<<(EE + TB - 1) / TB, TB>>>(ei, et);
    deg_kernel<<<(NN + TB - 1) / TB, TB>>>(batch);
    scan_kernel<<<1, 1024>>>();
    scatter_kernel<<<(EE + TB - 1) / TB, TB>>>(ei, et);
    xsplit_kernel<<<(NN * HH / 2 + TB - 1) / TB, TB>>>(x);

    int wpBlocks = (KTOT * NTILE + TB - 1) / TB;
    wprep_kernel<<<wpBlocks, TB>>>(bases[0], root[0], 0);
    wprep_kernel<<<wpBlocks, TB>>>(bases[1], root[1], 1);
    wprep_kernel<<<wpBlocks, TB>>>(bases[2], root[2], 2);

    int aggBlocks = (NN * 32 + TB - 1) / TB;

    // layer 1: agg(x16) -> z; gemm -> h1 (fp16 + bf16 hi/lo), relu
    agg_kernel<<<aggBlocks, TB>>>((const __half*)p_x16, comp[0]);
    tc_gemm_kernel<<<GEMM_GRID, 256, GEMM_SMEM>>>(
        (const __nv_bfloat16*)p_xh, (const __nv_bfloat16*)p_xl,
        (__half*)p_h116, (__nv_bfloat16*)p_h1h, (__nv_bfloat16*)p_h1l,
        bias[0], 1, 0, 0, batch);
    // layer 2: agg(h1_16) -> z; gemm -> h2 (fp16 + bf16 hi/lo), relu
    agg_kernel<<<aggBlocks, TB>>>((const __half*)p_h116, comp[1]);
    tc_gemm_kernel<<<GEMM_GRID, 256, GEMM_SMEM>>>(
        (const __nv_bfloat16*)p_h1h, (const __nv_bfloat16*)p_h1l,
        (__half*)p_h216, (__nv_bfloat16*)p_h2h, (__nv_bfloat16*)p_h2l,
        bias[1], 1, 1, 0, batch);
    // layer 3: agg(h2_16) -> z; gemm pools directly into d_pool, no relu
    agg_kernel<<<aggBlocks, TB>>>((const __half*)p_h216, comp[2]);
    tc_gemm_kernel<<<GEMM_GRID, 256, GEMM_SMEM>>>(
        (const __nv_bfloat16*)p_h2h, (const __nv_bfloat16*)p_h2l,
        (__half*)nullptr, (__nv_bfloat16*)nullptr, (__nv_bfloat16*)nullptr,
        bias[2], 0, 2, 1, batch);

    final_kernel<<<1, 128>>>(rl, relemb, lin_w, lin_b, out);
}